// round 13
// baseline (speedup 1.0000x reference)
#include <cuda_runtime.h>
#include <cuda_fp16.h>
#include <math.h>

// ---------------------------------------------------------------------------
#define BATCH   4
#define NTOK    2304
#define DMODEL  256
#define NHEADS  8
#define DK      32
#define DEPTH   3
#define KDROP   345
#define NKEEP   (NTOK - KDROP)     // 1959
#define NPAD    1984               // 31 * 64
#define MTOT    (BATCH * NTOK)     // 9216
#define NCHUNK  36

// weight scratch offsets (halfs), transposed [N][K] layout
#define OFF_QKV  0
#define OFF_PROJ 589824
#define OFF_MLP1 786432
#define OFF_MLP2 1572864
#define WTOT     2359296

// GEMM 5-stage pipeline smem (bytes): stage = A(MT*32 x 40) + B(128 x 40) halfs
#define GEMM_SMEM4 ((4 * 32 * 40 + 128 * 40) * 5 * 2)   // 102400
#define GEMM_SMEM2 ((2 * 32 * 40 + 128 * 40) * 5 * 2)   // 76800

// 1/sqrt(32) * log2(e), folded into Q at the QKV epilogue
#define SCALE2F 0.2550660030f

// ---------------------------------------------------------------------------
__device__ float  g_tokens[MTOT * DMODEL];
__device__ float  g_h     [MTOT * DMODEL];
__device__ __half g_hln   [MTOT * DMODEL];
__device__ __half g_qkv   [MTOT * 768];
__device__ __half g_attn  [MTOT * DMODEL];
__device__ __half g_mlp   [MTOT * 1024];
__device__ float  g_scores[MTOT];
__device__ int    g_mask  [MTOT];
__device__ int    g_idx   [BATCH * NPAD];
__device__ float  g_part  [BATCH * NCHUNK * DMODEL];
__device__ float2 g_stats [MTOT];
__device__ __half g_wt    [WTOT];

// ---------------------------------------------------------------------------
__device__ __forceinline__ unsigned packh2(float a, float b) {
    __half2 h = __floats2half2_rn(a, b);
    return *(unsigned*)&h;
}

__device__ __forceinline__ unsigned h2ex2(unsigned x) {
    unsigned r;
    asm("ex2.approx.f16x2 %0, %1;" : "=r"(r) : "r"(x));
    return r;
}

__device__ __forceinline__ void mma_f16(float c[4],
                                        unsigned a0, unsigned a1, unsigned a2, unsigned a3,
                                        unsigned b0, unsigned b1) {
    asm volatile(
        "mma.sync.aligned.m16n8k16.row.col.f32.f16.f16.f32 "
        "{%0,%1,%2,%3}, {%4,%5,%6,%7}, {%8,%9}, {%0,%1,%2,%3};"
        : "+f"(c[0]), "+f"(c[1]), "+f"(c[2]), "+f"(c[3])
        : "r"(a0), "r"(a1), "r"(a2), "r"(a3), "r"(b0), "r"(b1));
}

__device__ __forceinline__ void cpa16(void* smem, const void* g) {
    unsigned s = (unsigned)__cvta_generic_to_shared(smem);
    asm volatile("cp.async.ca.shared.global [%0], [%1], 16;" :: "r"(s), "l"(g));
}

__device__ __forceinline__ unsigned smaddr(const void* p) {
    return (unsigned)__cvta_generic_to_shared(p);
}

__device__ __forceinline__ void ldsm4(unsigned& r0, unsigned& r1, unsigned& r2, unsigned& r3,
                                      unsigned a) {
    asm volatile("ldmatrix.sync.aligned.m8n8.x4.shared.b16 {%0,%1,%2,%3}, [%4];"
                 : "=r"(r0), "=r"(r1), "=r"(r2), "=r"(r3) : "r"(a));
}

__device__ __forceinline__ void ldsm4t(unsigned& r0, unsigned& r1, unsigned& r2, unsigned& r3,
                                       unsigned a) {
    asm volatile("ldmatrix.sync.aligned.m8n8.x4.trans.shared.b16 {%0,%1,%2,%3}, [%4];"
                 : "=r"(r0), "=r"(r1), "=r"(r2), "=r"(r3) : "r"(a));
}

// ---------------------------------------------------------------------------
// Tiled transpose + f32->f16: W[L][K][N] -> WT[L][N][K] half
// ---------------------------------------------------------------------------
__global__ void transpose_w(const float* __restrict__ W, __half* __restrict__ WT,
                            int K, int N) {
    __shared__ float t[32][33];
    int n0 = blockIdx.x * 32, k0 = blockIdx.y * 32;
    int l = blockIdx.z;
    W  += (size_t)l * K * N;
    WT += (size_t)l * K * N;
    int tx = threadIdx.x, ty = threadIdx.y;
#pragma unroll
    for (int r = 0; r < 4; r++)
        t[ty + 8 * r][tx] = W[(size_t)(k0 + ty + 8 * r) * N + n0 + tx];
    __syncthreads();
#pragma unroll
    for (int r = 0; r < 4; r++)
        WT[(size_t)(n0 + ty + 8 * r) * K + k0 + tx] = __float2half(t[tx][ty + 8 * r]);
}

// ---------------------------------------------------------------------------
// Patch embed
// ---------------------------------------------------------------------------
__global__ void patch_kernel(const float* __restrict__ x,
                             const float* __restrict__ pw,
                             const float* __restrict__ pb,
                             const float* __restrict__ pos,
                             float* __restrict__ tokens) {
    int t = blockIdx.x;
    int b = t / NTOK, n = t % NTOK;
    int hc = n / 48, wc = n % 48;
    __shared__ float xs[12];
    if (threadIdx.x < 12) {
        int c = threadIdx.x / 4, pq = threadIdx.x % 4;
        int p = pq / 2, q = pq % 2;
        xs[threadIdx.x] = x[(((size_t)b * 3 + c) * 96 + (hc * 2 + p)) * 96 + (wc * 2 + q)];
    }
    __syncthreads();
    int d = threadIdx.x;
    float acc = pb[d];
#pragma unroll
    for (int e = 0; e < 12; e++) acc = fmaf(xs[e], pw[d * 12 + e], acc);
    tokens[(size_t)t * DMODEL + d] = acc + pos[(size_t)n * DMODEL + d];
}

// ---------------------------------------------------------------------------
// LayerNorm -> half output
// ---------------------------------------------------------------------------
__global__ void ln_half_kernel(const float* __restrict__ x,
                               const float* __restrict__ g,
                               const float* __restrict__ bta,
                               __half* __restrict__ y) {
    int t = blockIdx.x * 8 + (threadIdx.x >> 5);
    int lane = threadIdx.x & 31;
    const float* xp = x + (size_t)t * DMODEL + 8 * lane;
    float4 v0 = *(const float4*)xp;
    float4 v1 = *(const float4*)(xp + 4);
    float s = v0.x + v0.y + v0.z + v0.w + v1.x + v1.y + v1.z + v1.w;
#pragma unroll
    for (int o = 16; o > 0; o >>= 1) s += __shfl_xor_sync(0xffffffffu, s, o);
    float m = s * (1.0f / DMODEL);
    float vs = 0.f;
    float vv[8] = {v0.x, v0.y, v0.z, v0.w, v1.x, v1.y, v1.z, v1.w};
#pragma unroll
    for (int i = 0; i < 8; i++) { float d = vv[i] - m; vs = fmaf(d, d, vs); }
#pragma unroll
    for (int o = 16; o > 0; o >>= 1) vs += __shfl_xor_sync(0xffffffffu, vs, o);
    float rs = rsqrtf(vs * (1.0f / DMODEL) + 1e-5f);
    const float* gp = g + 8 * lane;
    const float* bp = bta + 8 * lane;
    __half2* yp = (__half2*)(y + (size_t)t * DMODEL + 8 * lane);
#pragma unroll
    for (int i = 0; i < 4; i++) {
        float g0 = gp[2 * i], g1 = gp[2 * i + 1];
        float b0 = bp[2 * i], b1 = bp[2 * i + 1];
        yp[i] = __floats2half2_rn((vv[2 * i] - m) * rs * g0 + b0,
                                  (vv[2 * i + 1] - m) * rs * g1 + b1);
    }
}

// ---------------------------------------------------------------------------
// LN stats (final LN only)
// ---------------------------------------------------------------------------
__global__ void ln_stats_kernel(const float* __restrict__ x, float2* __restrict__ st) {
    int t = blockIdx.x * 8 + (threadIdx.x >> 5);
    int lane = threadIdx.x & 31;
    const float* xp = x + (size_t)t * DMODEL;
    float v[8];
    float s = 0.f;
#pragma unroll
    for (int i = 0; i < 8; i++) { v[i] = xp[lane + 32 * i]; s += v[i]; }
#pragma unroll
    for (int o = 16; o > 0; o >>= 1) s += __shfl_xor_sync(0xffffffffu, s, o);
    float m = s * (1.0f / DMODEL);
    float vs = 0.f;
#pragma unroll
    for (int i = 0; i < 8; i++) { float d = v[i] - m; vs = fmaf(d, d, vs); }
#pragma unroll
    for (int o = 16; o > 0; o >>= 1) vs += __shfl_xor_sync(0xffffffffu, vs, o);
    float rs = rsqrtf(vs * (1.0f / DMODEL) + 1e-5f);
    if (lane == 0) { float2 o2 = {m, rs}; st[t] = o2; }
}

// ---------------------------------------------------------------------------
// fp32 FFMA GEMM + relu (importance path only: exact)
// ---------------------------------------------------------------------------
__global__ void gemm_f32_relu(const float* __restrict__ A,
                              const float* __restrict__ Bw,
                              const float* __restrict__ bias,
                              float* __restrict__ C,
                              int M, int N, int K) {
    __shared__ float As[16][68];
    __shared__ float Bs[16][68];
    int m0 = blockIdx.y * 64, n0 = blockIdx.x * 64;
    int tid = threadIdx.x;
    int tm = (tid >> 4) * 4, tn = (tid & 15) * 4;
    int arow = tid >> 2, ak4 = tid & 3;
    int bk = tid >> 4, bn4 = tid & 15;

    float acc[4][4] = {};
    for (int k0 = 0; k0 < K; k0 += 16) {
        __syncthreads();
        float4 av = *(const float4*)(A + (size_t)(m0 + arow) * K + k0 + ak4 * 4);
        As[ak4 * 4 + 0][arow] = av.x;
        As[ak4 * 4 + 1][arow] = av.y;
        As[ak4 * 4 + 2][arow] = av.z;
        As[ak4 * 4 + 3][arow] = av.w;
        float4 bv = *(const float4*)(Bw + (size_t)(k0 + bk) * N + n0 + bn4 * 4);
        *(float4*)&Bs[bk][bn4 * 4] = bv;
        __syncthreads();
#pragma unroll
        for (int k = 0; k < 16; k++) {
            float4 aa = *(const float4*)&As[k][tm];
            float4 bb = *(const float4*)&Bs[k][tn];
            float a4[4] = {aa.x, aa.y, aa.z, aa.w};
            float b4[4] = {bb.x, bb.y, bb.z, bb.w};
#pragma unroll
            for (int i = 0; i < 4; i++)
#pragma unroll
                for (int j = 0; j < 4; j++)
                    acc[i][j] = fmaf(a4[i], b4[j], acc[i][j]);
        }
    }
    float4 bv = *(const float4*)(bias + n0 + tn);
    float bias4[4] = {bv.x, bv.y, bv.z, bv.w};
#pragma unroll
    for (int i = 0; i < 4; i++) {
        size_t base = (size_t)(m0 + tm + i) * N + n0 + tn;
        float4 ov;
        ov.x = fmaxf(acc[i][0] + bias4[0], 0.f);
        ov.y = fmaxf(acc[i][1] + bias4[1], 0.f);
        ov.z = fmaxf(acc[i][2] + bias4[2], 0.f);
        ov.w = fmaxf(acc[i][3] + bias4[3], 0.f);
        *(float4*)(C + base) = ov;
    }
}

// ---------------------------------------------------------------------------
// FP16 tensor-core GEMM, 5-stage cp.async pipeline, ldmatrix fragments.
// Tile (MT*32)x128, BK=32, 256 threads. MT=4: warp tile 64x32; MT=2: 32x32.
// OUT_QKV: half out with Q columns (col<256) pre-scaled by 1/sqrt(dk)*log2e.
// ---------------------------------------------------------------------------
enum { OUT_HALF = 0, OUT_GELU = 1, OUT_RES = 2, OUT_QKV = 3 };

template <int OUT, int MT>
__global__ __launch_bounds__(256, 2) void gemm_fp16(const __half* __restrict__ A,
                                                    const __half* __restrict__ WT,
                                                    const float* __restrict__ bias,
                                                    const float* res,
                                                    float* C,
                                                    __half* hout,
                                                    int M, int N, int K) {
    extern __shared__ __half dsm[];
    constexpr int ASTG = MT * 32 * 40;   // halfs per A stage
    constexpr int BSTG = 128 * 40;       // halfs per B stage
    constexpr int STG  = ASTG + BSTG;

    int m0 = blockIdx.y * (MT * 32), n0 = blockIdx.x * 128;
    int tid = threadIdx.x, warp = tid >> 5, lane = tid & 31;
    int tq = lane >> 2, tc = lane & 3;
    int mb = (warp >> 2) * (MT * 16), nb = (warp & 3) * 32;

    int aR = mb + (lane & 15);
    int aC = (lane >> 4) * 8;
    int bR = nb + ((lane >> 4) & 1) * 8 + (lane & 7);
    int bC = ((lane >> 3) & 1) * 8;

    // loaders: B = 128 rows x 32 halfs; A = MT*32 rows x 32 halfs
    int brow = tid >> 1, bseg = (tid & 1) * 16;
    int arow = (MT == 4) ? (tid >> 1) : (tid >> 2);
    int aseg = (MT == 4) ? (tid & 1) * 16 : (tid & 3) * 8;
    const __half* ap = A + (size_t)(m0 + arow) * K + aseg;
    const __half* bp = WT + (size_t)(n0 + brow) * K + bseg;

    auto issue = [&](int it) {
        int s = it % 5, k0 = it * 32;
        __half* A_s = dsm + s * STG + arow * 40 + aseg;
        __half* B_s = dsm + s * STG + ASTG + brow * 40 + bseg;
        cpa16(A_s, ap + k0);
        if (MT == 4) cpa16(A_s + 8, ap + k0 + 8);
        cpa16(B_s, bp + k0);
        cpa16(B_s + 8, bp + k0 + 8);
        asm volatile("cp.async.commit_group;");
    };

    float acc[MT][4][4] = {};
    int KT = K / 32;   // >= 8 for all uses

    issue(0); issue(1); issue(2); issue(3);

    for (int it = 0; it < KT; ++it) {
        if (it + 4 < KT) asm volatile("cp.async.wait_group 3;");
        else             asm volatile("cp.async.wait_group 0;");
        __syncthreads();
        if (it + 4 < KT) issue(it + 4);

        const __half* A_s = dsm + (it % 5) * STG;
        const __half* B_s = A_s + ASTG;
#pragma unroll
        for (int ks = 0; ks < 2; ks++) {
            int kk = ks * 16;
            unsigned a[MT][4], b[4][2];
#pragma unroll
            for (int mt = 0; mt < MT; mt++)
                ldsm4(a[mt][0], a[mt][1], a[mt][2], a[mt][3],
                      smaddr(A_s + (aR + 16 * mt) * 40 + kk + aC));
#pragma unroll
            for (int p = 0; p < 2; p++)
                ldsm4(b[2 * p][0], b[2 * p][1], b[2 * p + 1][0], b[2 * p + 1][1],
                      smaddr(B_s + (bR + 16 * p) * 40 + kk + bC));
#pragma unroll
            for (int mt = 0; mt < MT; mt++)
#pragma unroll
                for (int nt = 0; nt < 4; nt++)
                    mma_f16(acc[mt][nt], a[mt][0], a[mt][1], a[mt][2], a[mt][3],
                            b[nt][0], b[nt][1]);
        }
    }

#pragma unroll
    for (int mt = 0; mt < MT; mt++) {
#pragma unroll
        for (int nt = 0; nt < 4; nt++) {
            int col = n0 + nb + 8 * nt + 2 * tc;
            float2 bb = *(const float2*)(bias + col);
#pragma unroll
            for (int hh = 0; hh < 2; hh++) {
                int row = m0 + mb + 16 * mt + tq + hh * 8;
                float u0 = acc[mt][nt][hh * 2 + 0] + bb.x;
                float u1 = acc[mt][nt][hh * 2 + 1] + bb.y;
                if (OUT == OUT_GELU) {
                    u0 = 0.5f * u0 * (1.0f + erff(u0 * 0.70710678118654752f));
                    u1 = 0.5f * u1 * (1.0f + erff(u1 * 0.70710678118654752f));
                }
                if (OUT == OUT_QKV && col < 256) {
                    u0 *= SCALE2F;
                    u1 *= SCALE2F;
                }
                if (OUT == OUT_RES) {
                    size_t base = (size_t)row * N + col;
                    float2 rr = *(const float2*)(res + base);
                    float2 ov = {u0 + rr.x, u1 + rr.y};
                    *(float2*)(C + base) = ov;
                } else {
                    *(__half2*)(hout + (size_t)row * N + col) = __floats2half2_rn(u0, u1);
                }
            }
        }
    }
}

// ---------------------------------------------------------------------------
// Importance scores
// ---------------------------------------------------------------------------
__global__ void score_kernel(const float* __restrict__ h,
                             const float* __restrict__ w2,
                             const float* __restrict__ b2,
                             float* __restrict__ scores) {
    int t = blockIdx.x * 8 + (threadIdx.x >> 5);
    int lane = threadIdx.x & 31;
    const float* hp = h + (size_t)t * DMODEL;
    float s = 0.f;
#pragma unroll
    for (int i = 0; i < 8; i++) s = fmaf(hp[lane + 32 * i], w2[lane + 32 * i], s);
#pragma unroll
    for (int o = 16; o > 0; o >>= 1) s += __shfl_xor_sync(0xffffffffu, s, o);
    if (lane == 0) scores[t] = 1.0f / (1.0f + __expf(-(s + b2[0])));
}

// ---------------------------------------------------------------------------
// Bottom-k mask + compaction
// ---------------------------------------------------------------------------
__global__ void mask_kernel(const float* __restrict__ scores, int* __restrict__ mask) {
    int t = blockIdx.x * 8 + (threadIdx.x >> 5);
    int lane = threadIdx.x & 31;
    int b = t / NTOK, i = t % NTOK;
    const float* sb = scores + b * NTOK;
    float si = sb[i];
    int cnt = 0;
#pragma unroll 4
    for (int j = lane; j < NTOK; j += 32) {
        float sj = sb[j];
        cnt += (sj < si) || (sj == si && j < i);
    }
#pragma unroll
    for (int o = 16; o > 0; o >>= 1) cnt += __shfl_xor_sync(0xffffffffu, cnt, o);
    if (lane == 0) mask[t] = (cnt < KDROP) ? 1 : 0;
}

__global__ void compact_kernel(const int* __restrict__ mask, int* __restrict__ idx) {
    int b = blockIdx.x, tid = threadIdx.x;
    int lane = tid & 31, w = tid >> 5;
    const int* mb = mask + b * NTOK;
    int base = tid * 9;
    int keep[9], cnt = 0;
#pragma unroll
    for (int i = 0; i < 9; i++) {
        keep[i] = (mb[base + i] == 0);
        cnt += keep[i];
    }
    int inc = cnt;
#pragma unroll
    for (int o = 1; o < 32; o <<= 1) {
        int n = __shfl_up_sync(0xffffffffu, inc, o);
        if (lane >= o) inc += n;
    }
    __shared__ int wsum[8];
    if (lane == 31) wsum[w] = inc;
    __syncthreads();
    int woff = 0;
    for (int j = 0; j < w; j++) woff += wsum[j];
    int off = woff + inc - cnt;
    int* ob = idx + b * NPAD;
#pragma unroll
    for (int i = 0; i < 9; i++)
        if (keep[i]) ob[off++] = base + i;
    if (tid < NPAD - NKEEP) ob[NKEEP + tid] = 0;
}

// ---------------------------------------------------------------------------
// FP16 flash attention, 256-query tile, 3-stage async K/V pipeline.
// Max-free softmax, half2 exp2, ldmatrix frags, V via ldmatrix.trans.
// 256 threads: warp owns 32 q-rows (2 x 16-row groups).
// ---------------------------------------------------------------------------
__global__ __launch_bounds__(256, 2) void attn_fp16(const __half* __restrict__ qkv,
                                                    const int* __restrict__ idx,
                                                    __half* __restrict__ out) {
    __shared__ __half Ks[3][64][40];
    __shared__ __half Vs[3][64][40];
    __shared__ int    sidx[NPAD];

    int b = blockIdx.z, h = blockIdx.y;
    int q0 = blockIdx.x * 256;
    int tid = threadIdx.x;
    int w = tid >> 5, lane = tid & 31;
    int tq = lane >> 2, tc = lane & 3;
    int hoff = h * DK;

    int bR = ((lane >> 4) & 1) * 8 + (lane & 7);
    int bC = ((lane >> 3) & 1) * 8;
    int vR = lane & 15;
    int vC = (lane >> 4) * 8;

    const __half* qb = qkv + (size_t)b * NTOK * 768;

    for (int j = tid; j < NPAD; j += 256) sidx[j] = idx[b * NPAD + j];

    // Q fragments for both 16-row groups
    unsigned qa[2][2][4];
#pragma unroll
    for (int g = 0; g < 2; g++) {
        int rg = q0 + w * 32 + g * 16 + tq;
#pragma unroll
        for (int ks = 0; ks < 2; ks++) {
            int col = hoff + ks * 16 + 2 * tc;
            qa[g][ks][0] = *(const unsigned*)(qb + (size_t)rg * 768 + col);
            qa[g][ks][1] = *(const unsigned*)(qb + (size_t)(rg + 8) * 768 + col);
            qa[g][ks][2] = *(const unsigned*)(qb + (size_t)rg * 768 + col + 8);
            qa[g][ks][3] = *(const unsigned*)(qb + (size_t)(rg + 8) * 768 + col + 8);
        }
    }
    __syncthreads();   // sidx ready

    int krow = tid >> 2, kseg = tid & 3;
    auto issue = [&](int buf, int c0) {
        int t = sidx[c0 + krow];
        const __half* base = qb + (size_t)t * 768 + hoff + kseg * 8;
        cpa16(&Ks[buf][krow][kseg * 8], base + 256);
        cpa16(&Vs[buf][krow][kseg * 8], base + 512);
        asm volatile("cp.async.commit_group;");
    };

    const int NCH = NPAD / 64;
    issue(0, 0);
    issue(1, 64);

    float lsum[4] = {0.f, 0.f, 0.f, 0.f};
    float oacc[2][4][4] = {};

    for (int ci = 0; ci < NCH; ci++) {
        int buf = ci % 3;
        if (ci + 1 < NCH) asm volatile("cp.async.wait_group 1;");
        else              asm volatile("cp.async.wait_group 0;");
        __syncthreads();
        if (ci + 2 < NCH) issue((ci + 2) % 3, (ci + 2) * 64);

        unsigned pe[2][8], po[2][8];
#pragma unroll
        for (int g = 0; g < 2; g++) {
            // S = Q K^T for this q-group
            float sacc[8][4] = {};
#pragma unroll
            for (int ks = 0; ks < 2; ks++) {
                int kk = ks * 16;
                unsigned kb[8][2];
#pragma unroll
                for (int p = 0; p < 4; p++)
                    ldsm4(kb[2 * p][0], kb[2 * p][1], kb[2 * p + 1][0], kb[2 * p + 1][1],
                          smaddr(&Ks[buf][bR + 16 * p][kk + bC]));
#pragma unroll
                for (int nt = 0; nt < 8; nt++)
                    mma_f16(sacc[nt], qa[g][ks][0], qa[g][ks][1], qa[g][ks][2],
                            qa[g][ks][3], kb[nt][0], kb[nt][1]);
            }

            // pad mask only needed in the final chunk (exp2(-126) -> 0 in fp16)
            if (ci == NCH - 1) {
                int c0 = ci * 64;
#pragma unroll
                for (int nt = 0; nt < 8; nt++) {
                    int jj = c0 + 8 * nt + 2 * tc;
                    if (jj >= NKEEP)     { sacc[nt][0] = -126.f; sacc[nt][2] = -126.f; }
                    if (jj + 1 >= NKEEP) { sacc[nt][1] = -126.f; sacc[nt][3] = -126.f; }
                }
            }

            // half2 exp2; l accumulated as bounded half2 subtotals -> fp32
            __half2 lh0 = __float2half2_rn(0.f), lh1 = __float2half2_rn(0.f);
#pragma unroll
            for (int nt = 0; nt < 8; nt++) {
                pe[g][nt] = h2ex2(packh2(sacc[nt][0], sacc[nt][1]));
                po[g][nt] = h2ex2(packh2(sacc[nt][2], sacc[nt][3]));
                lh0 = __hadd2(lh0, *(__half2*)&pe[g][nt]);
                lh1 = __hadd2(lh1, *(__half2*)&po[g][nt]);
            }
            float2 lf0 = __half22float2(lh0);
            float2 lf1 = __half22float2(lh1);
            lsum[2 * g + 0] += lf0.x + lf0.y;
            lsum[2 * g + 1] += lf1.x + lf1.y;
        }

        // O += P V : V fragments loaded once, reused by both q-groups
#pragma unroll
        for (int ks2 = 0; ks2 < 4; ks2++) {
            int kk = ks2 * 16;
            unsigned vb[4][2];
#pragma unroll
            for (int p = 0; p < 2; p++)
                ldsm4t(vb[2 * p][0], vb[2 * p][1], vb[2 * p + 1][0], vb[2 * p + 1][1],
                       smaddr(&Vs[buf][kk + vR][16 * p + vC]));
#pragma unroll
            for (int nt = 0; nt < 4; nt++) {
                mma_f16(oacc[0][nt], pe[0][2 * ks2], po[0][2 * ks2],
                        pe[0][2 * ks2 + 1], po[0][2 * ks2 + 1], vb[nt][0], vb[nt][1]);
                mma_f16(oacc[1][nt], pe[1][2 * ks2], po[1][2 * ks2],
                        pe[1][2 * ks2 + 1], po[1][2 * ks2 + 1], vb[nt][0], vb[nt][1]);
            }
        }
    }

    // end-of-loop l reduction across the 4 lanes sharing each row
#pragma unroll
    for (int i = 0; i < 4; i++) {
        lsum[i] += __shfl_xor_sync(0xffffffffu, lsum[i], 1);
        lsum[i] += __shfl_xor_sync(0xffffffffu, lsum[i], 2);
    }

#pragma unroll
    for (int g = 0; g < 2; g++) {
        float inv0 = 1.0f / lsum[2 * g + 0], inv1 = 1.0f / lsum[2 * g + 1];
        int r0 = b * NTOK + q0 + w * 32 + g * 16 + tq;
#pragma unroll
        for (int nt = 0; nt < 4; nt++) {
            int col = hoff + 8 * nt + 2 * tc;
            *(__half2*)(out + (size_t)r0 * DMODEL + col) =
                __floats2half2_rn(oacc[g][nt][0] * inv0, oacc[g][nt][1] * inv0);
            *(__half2*)(out + (size_t)(r0 + 8) * DMODEL + col) =
                __floats2half2_rn(oacc[g][nt][2] * inv1, oacc[g][nt][3] * inv1);
        }
    }
}

// ---------------------------------------------------------------------------
// Final LN + mean
// ---------------------------------------------------------------------------
__global__ void mean1_kernel(const float* __restrict__ x, const float2* __restrict__ st,
                             float* __restrict__ part) {
    int b = blockIdx.y, ch = blockIdx.x, d = threadIdx.x;
    const float* p = x + ((size_t)b * NTOK + ch * 64) * DMODEL + d;
    const float2* sp = st + b * NTOK + ch * 64;
    float s = 0.f;
#pragma unroll 8
    for (int n = 0; n < 64; n++) {
        float2 ms = sp[n];
        s += (p[(size_t)n * DMODEL] - ms.x) * ms.y;
    }
    part[((size_t)b * NCHUNK + ch) * DMODEL + d] = s;
}

__global__ void mean2_kernel(const float* __restrict__ part,
                             const float* __restrict__ g,
                             const float* __restrict__ bo,
                             float* __restrict__ out) {
    int b = blockIdx.x, d = threadIdx.x;
    float s = 0.f;
    for (int c = 0; c < NCHUNK; c++) s += part[((size_t)b * NCHUNK + c) * DMODEL + d];
    out[b * DMODEL + d] = s * (1.0f / NTOK) * g[d] + bo[d];
}

// ---------------------------------------------------------------------------
// Launcher
// ---------------------------------------------------------------------------
extern "C" void kernel_launch(void* const* d_in, const int* in_sizes, int n_in,
                              void* d_out, int out_size) {
    const float* x       = (const float*)d_in[0];
    const float* patch_w = (const float*)d_in[1];
    const float* patch_b = (const float*)d_in[2];
    const float* pos     = (const float*)d_in[3];
    const float* imp_w1  = (const float*)d_in[4];
    const float* imp_b1  = (const float*)d_in[5];
    const float* imp_w2  = (const float*)d_in[6];
    const float* imp_b2  = (const float*)d_in[7];
    const float* ln1_g   = (const float*)d_in[8];
    const float* ln1_b   = (const float*)d_in[9];
    const float* qkv_w   = (const float*)d_in[10];
    const float* qkv_b   = (const float*)d_in[11];
    const float* proj_w  = (const float*)d_in[12];
    const float* proj_b  = (const float*)d_in[13];
    const float* ln2_g   = (const float*)d_in[14];
    const float* ln2_b   = (const float*)d_in[15];
    const float* mlp_w1  = (const float*)d_in[16];
    const float* mlp_b1  = (const float*)d_in[17];
    const float* mlp_w2  = (const float*)d_in[18];
    const float* mlp_b2  = (const float*)d_in[19];
    const float* out_g   = (const float*)d_in[20];
    const float* out_b   = (const float*)d_in[21];
    float* out = (float*)d_out;

    float *tokens, *hbuf, *scores, *part;
    __half *hln, *qkv, *attn, *mlp, *wt;
    float2* stats;
    int *mask, *idx;
    cudaGetSymbolAddress((void**)&tokens, g_tokens);
    cudaGetSymbolAddress((void**)&hbuf,   g_h);
    cudaGetSymbolAddress((void**)&hln,    g_hln);
    cudaGetSymbolAddress((void**)&qkv,    g_qkv);
    cudaGetSymbolAddress((void**)&attn,   g_attn);
    cudaGetSymbolAddress((void**)&mlp,    g_mlp);
    cudaGetSymbolAddress((void**)&scores, g_scores);
    cudaGetSymbolAddress((void**)&mask,   g_mask);
    cudaGetSymbolAddress((void**)&idx,    g_idx);
    cudaGetSymbolAddress((void**)&part,   g_part);
    cudaGetSymbolAddress((void**)&stats,  g_stats);
    cudaGetSymbolAddress((void**)&wt,     g_wt);

    cudaFuncSetAttribute((const void*)gemm_fp16<OUT_QKV, 4>,
                         cudaFuncAttributeMaxDynamicSharedMemorySize, GEMM_SMEM4);
    cudaFuncSetAttribute((const void*)gemm_fp16<OUT_GELU, 4>,
                         cudaFuncAttributeMaxDynamicSharedMemorySize, GEMM_SMEM4);
    cudaFuncSetAttribute((const void*)gemm_fp16<OUT_RES, 2>,
                         cudaFuncAttributeMaxDynamicSharedMemorySize, GEMM_SMEM2);

    dim3 tb(32, 8);

    transpose_w<<<dim3(24, 8, 3), tb>>>(qkv_w, wt + OFF_QKV, DMODEL, 768);              // 0
    patch_kernel<<<MTOT, 256>>>(x, patch_w, patch_b, pos, tokens);                       // 1
    ln_half_kernel<<<MTOT / 8, 256>>>(tokens, ln1_g, ln1_b, hln);                        // 2
    gemm_fp16<OUT_QKV, 4><<<dim3(6, 72), 256, GEMM_SMEM4>>>(
        hln, wt + OFF_QKV, qkv_b, nullptr, nullptr, qkv, MTOT, 768, DMODEL);             // 3 (profiled)
    transpose_w<<<dim3(8, 8, 3), tb>>>(proj_w, wt + OFF_PROJ, DMODEL, DMODEL);           // 4
    transpose_w<<<dim3(32, 8, 3), tb>>>(mlp_w1, wt + OFF_MLP1, DMODEL, 1024);            // 5
    transpose_w<<<dim3(8, 32, 3), tb>>>(mlp_w2, wt + OFF_MLP2, 1024, DMODEL);            // 6
    gemm_f32_relu<<<dim3(DMODEL / 64, MTOT / 64), 256>>>(tokens, imp_w1, imp_b1,
                                                         hbuf, MTOT, DMODEL, DMODEL);    // 7
    score_kernel<<<MTOT / 8, 256>>>(hbuf, imp_w2, imp_b2, scores);                       // 8
    mask_kernel<<<MTOT / 8, 256>>>(scores, mask);                                        // 9
    compact_kernel<<<BATCH, 256>>>(mask, idx);                                           // 10

    for (int l = 0; l < DEPTH; l++) {
        if (l > 0) {
            ln_half_kernel<<<MTOT / 8, 256>>>(tokens, ln1_g + l * DMODEL,
                                              ln1_b + l * DMODEL, hln);
            gemm_fp16<OUT_QKV, 4><<<dim3(6, 72), 256, GEMM_SMEM4>>>(
                hln, wt + OFF_QKV + (size_t)l * DMODEL * 768, qkv_b + l * 768,
                nullptr, nullptr, qkv, MTOT, 768, DMODEL);
        }
        attn_fp16<<<dim3(NTOK / 256, NHEADS, BATCH), 256>>>(qkv, idx, attn);
        gemm_fp16<OUT_RES, 2><<<dim3(2, 144), 256, GEMM_SMEM2>>>(
            attn, wt + OFF_PROJ + (size_t)l * DMODEL * DMODEL, proj_b + l * DMODEL,
            tokens, tokens, nullptr, MTOT, DMODEL, DMODEL);
        ln_half_kernel<<<MTOT / 8, 256>>>(tokens, ln2_g + l * DMODEL,
                                          ln2_b + l * DMODEL, hln);
        gemm_fp16<OUT_GELU, 4><<<dim3(8, 72), 256, GEMM_SMEM4>>>(
            hln, wt + OFF_MLP1 + (size_t)l * DMODEL * 1024, mlp_b1 + l * 1024,
            nullptr, nullptr, mlp, MTOT, 1024, DMODEL);
        gemm_fp16<OUT_RES, 2><<<dim3(2, 144), 256, GEMM_SMEM2>>>(
            mlp, wt + OFF_MLP2 + (size_t)l * 1024 * DMODEL, mlp_b2 + l * DMODEL,
            tokens, tokens, nullptr, MTOT, DMODEL, 1024);
    }

    ln_stats_kernel<<<MTOT / 8, 256>>>(tokens, stats);
    mean1_kernel<<<dim3(NCHUNK, BATCH), 256>>>(tokens, stats, part);
    mean2_kernel<<<BATCH, 256>>>(part, out_g, out_b, out);
}

// round 14
// speedup vs baseline: 1.0686x; 1.0686x over previous
#include <cuda_runtime.h>
#include <cuda_fp16.h>
#include <math.h>

// ---------------------------------------------------------------------------
#define BATCH   4
#define NTOK    2304
#define DMODEL  256
#define NHEADS  8
#define DK      32
#define DEPTH   3
#define KDROP   345
#define NKEEP   (NTOK - KDROP)     // 1959
#define NPAD    1984               // 31 * 64
#define MTOT    (BATCH * NTOK)     // 9216
#define NCHUNK  36

// weight scratch offsets (halfs), transposed [N][K] layout
#define OFF_QKV  0
#define OFF_PROJ 589824
#define OFF_MLP1 786432
#define OFF_MLP2 1572864
#define WTOT     2359296

// GEMM 3-stage pipeline smem (bytes): stage = A(MT*32 x 40) + B(128 x 40) halfs
#define GEMM_SMEM(MT) (((MT) * 32 * 40 + 128 * 40) * 3 * 2)

// 1/sqrt(32) * log2(e), folded into Q at the QKV epilogue
#define SCALE2F 0.2550660030f

// ---------------------------------------------------------------------------
__device__ float  g_tokens[MTOT * DMODEL];
__device__ float  g_h     [MTOT * DMODEL];
__device__ __half g_hln   [MTOT * DMODEL];
__device__ __half g_qkv   [MTOT * 768];
__device__ __half g_attn  [MTOT * DMODEL];
__device__ __half g_mlp   [MTOT * 1024];
__device__ float  g_scores[MTOT];
__device__ int    g_mask  [MTOT];
__device__ int    g_idx   [BATCH * NPAD];
__device__ float  g_part  [BATCH * NCHUNK * DMODEL];
__device__ float2 g_stats [MTOT];
__device__ __half g_wt    [WTOT];

// ---------------------------------------------------------------------------
__device__ __forceinline__ unsigned packh2(float a, float b) {
    __half2 h = __floats2half2_rn(a, b);
    return *(unsigned*)&h;
}

__device__ __forceinline__ unsigned h2ex2(unsigned x) {
    unsigned r;
    asm("ex2.approx.f16x2 %0, %1;" : "=r"(r) : "r"(x));
    return r;
}

__device__ __forceinline__ void mma_f16(float c[4],
                                        unsigned a0, unsigned a1, unsigned a2, unsigned a3,
                                        unsigned b0, unsigned b1) {
    asm volatile(
        "mma.sync.aligned.m16n8k16.row.col.f32.f16.f16.f32 "
        "{%0,%1,%2,%3}, {%4,%5,%6,%7}, {%8,%9}, {%0,%1,%2,%3};"
        : "+f"(c[0]), "+f"(c[1]), "+f"(c[2]), "+f"(c[3])
        : "r"(a0), "r"(a1), "r"(a2), "r"(a3), "r"(b0), "r"(b1));
}

__device__ __forceinline__ void cpa16(void* smem, const void* g) {
    unsigned s = (unsigned)__cvta_generic_to_shared(smem);
    asm volatile("cp.async.ca.shared.global [%0], [%1], 16;" :: "r"(s), "l"(g));
}

__device__ __forceinline__ unsigned smaddr(const void* p) {
    return (unsigned)__cvta_generic_to_shared(p);
}

__device__ __forceinline__ void ldsm4(unsigned& r0, unsigned& r1, unsigned& r2, unsigned& r3,
                                      unsigned a) {
    asm volatile("ldmatrix.sync.aligned.m8n8.x4.shared.b16 {%0,%1,%2,%3}, [%4];"
                 : "=r"(r0), "=r"(r1), "=r"(r2), "=r"(r3) : "r"(a));
}

__device__ __forceinline__ void ldsm4t(unsigned& r0, unsigned& r1, unsigned& r2, unsigned& r3,
                                       unsigned a) {
    asm volatile("ldmatrix.sync.aligned.m8n8.x4.trans.shared.b16 {%0,%1,%2,%3}, [%4];"
                 : "=r"(r0), "=r"(r1), "=r"(r2), "=r"(r3) : "r"(a));
}

// ---------------------------------------------------------------------------
// Tiled transpose + f32->f16: W[L][K][N] -> WT[L][N][K] half
// ---------------------------------------------------------------------------
__global__ void transpose_w(const float* __restrict__ W, __half* __restrict__ WT,
                            int K, int N) {
    __shared__ float t[32][33];
    int n0 = blockIdx.x * 32, k0 = blockIdx.y * 32;
    int l = blockIdx.z;
    W  += (size_t)l * K * N;
    WT += (size_t)l * K * N;
    int tx = threadIdx.x, ty = threadIdx.y;
#pragma unroll
    for (int r = 0; r < 4; r++)
        t[ty + 8 * r][tx] = W[(size_t)(k0 + ty + 8 * r) * N + n0 + tx];
    __syncthreads();
#pragma unroll
    for (int r = 0; r < 4; r++)
        WT[(size_t)(n0 + ty + 8 * r) * K + k0 + tx] = __float2half(t[tx][ty + 8 * r]);
}

// ---------------------------------------------------------------------------
// Patch embed
// ---------------------------------------------------------------------------
__global__ void patch_kernel(const float* __restrict__ x,
                             const float* __restrict__ pw,
                             const float* __restrict__ pb,
                             const float* __restrict__ pos,
                             float* __restrict__ tokens) {
    int t = blockIdx.x;
    int b = t / NTOK, n = t % NTOK;
    int hc = n / 48, wc = n % 48;
    __shared__ float xs[12];
    if (threadIdx.x < 12) {
        int c = threadIdx.x / 4, pq = threadIdx.x % 4;
        int p = pq / 2, q = pq % 2;
        xs[threadIdx.x] = x[(((size_t)b * 3 + c) * 96 + (hc * 2 + p)) * 96 + (wc * 2 + q)];
    }
    __syncthreads();
    int d = threadIdx.x;
    float acc = pb[d];
#pragma unroll
    for (int e = 0; e < 12; e++) acc = fmaf(xs[e], pw[d * 12 + e], acc);
    tokens[(size_t)t * DMODEL + d] = acc + pos[(size_t)n * DMODEL + d];
}

// ---------------------------------------------------------------------------
// LayerNorm -> half output
// ---------------------------------------------------------------------------
__global__ void ln_half_kernel(const float* __restrict__ x,
                               const float* __restrict__ g,
                               const float* __restrict__ bta,
                               __half* __restrict__ y) {
    int t = blockIdx.x * 8 + (threadIdx.x >> 5);
    int lane = threadIdx.x & 31;
    const float* xp = x + (size_t)t * DMODEL + 8 * lane;
    float4 v0 = *(const float4*)xp;
    float4 v1 = *(const float4*)(xp + 4);
    float s = v0.x + v0.y + v0.z + v0.w + v1.x + v1.y + v1.z + v1.w;
#pragma unroll
    for (int o = 16; o > 0; o >>= 1) s += __shfl_xor_sync(0xffffffffu, s, o);
    float m = s * (1.0f / DMODEL);
    float vs = 0.f;
    float vv[8] = {v0.x, v0.y, v0.z, v0.w, v1.x, v1.y, v1.z, v1.w};
#pragma unroll
    for (int i = 0; i < 8; i++) { float d = vv[i] - m; vs = fmaf(d, d, vs); }
#pragma unroll
    for (int o = 16; o > 0; o >>= 1) vs += __shfl_xor_sync(0xffffffffu, vs, o);
    float rs = rsqrtf(vs * (1.0f / DMODEL) + 1e-5f);
    const float* gp = g + 8 * lane;
    const float* bp = bta + 8 * lane;
    __half2* yp = (__half2*)(y + (size_t)t * DMODEL + 8 * lane);
#pragma unroll
    for (int i = 0; i < 4; i++) {
        float g0 = gp[2 * i], g1 = gp[2 * i + 1];
        float b0 = bp[2 * i], b1 = bp[2 * i + 1];
        yp[i] = __floats2half2_rn((vv[2 * i] - m) * rs * g0 + b0,
                                  (vv[2 * i + 1] - m) * rs * g1 + b1);
    }
}

// ---------------------------------------------------------------------------
// LN stats (final LN only)
// ---------------------------------------------------------------------------
__global__ void ln_stats_kernel(const float* __restrict__ x, float2* __restrict__ st) {
    int t = blockIdx.x * 8 + (threadIdx.x >> 5);
    int lane = threadIdx.x & 31;
    const float* xp = x + (size_t)t * DMODEL;
    float v[8];
    float s = 0.f;
#pragma unroll
    for (int i = 0; i < 8; i++) { v[i] = xp[lane + 32 * i]; s += v[i]; }
#pragma unroll
    for (int o = 16; o > 0; o >>= 1) s += __shfl_xor_sync(0xffffffffu, s, o);
    float m = s * (1.0f / DMODEL);
    float vs = 0.f;
#pragma unroll
    for (int i = 0; i < 8; i++) { float d = v[i] - m; vs = fmaf(d, d, vs); }
#pragma unroll
    for (int o = 16; o > 0; o >>= 1) vs += __shfl_xor_sync(0xffffffffu, vs, o);
    float rs = rsqrtf(vs * (1.0f / DMODEL) + 1e-5f);
    if (lane == 0) { float2 o2 = {m, rs}; st[t] = o2; }
}

// ---------------------------------------------------------------------------
// fp32 FFMA GEMM + relu (importance path only: exact)
// ---------------------------------------------------------------------------
__global__ void gemm_f32_relu(const float* __restrict__ A,
                              const float* __restrict__ Bw,
                              const float* __restrict__ bias,
                              float* __restrict__ C,
                              int M, int N, int K) {
    __shared__ float As[16][68];
    __shared__ float Bs[16][68];
    int m0 = blockIdx.y * 64, n0 = blockIdx.x * 64;
    int tid = threadIdx.x;
    int tm = (tid >> 4) * 4, tn = (tid & 15) * 4;
    int arow = tid >> 2, ak4 = tid & 3;
    int bk = tid >> 4, bn4 = tid & 15;

    float acc[4][4] = {};
    for (int k0 = 0; k0 < K; k0 += 16) {
        __syncthreads();
        float4 av = *(const float4*)(A + (size_t)(m0 + arow) * K + k0 + ak4 * 4);
        As[ak4 * 4 + 0][arow] = av.x;
        As[ak4 * 4 + 1][arow] = av.y;
        As[ak4 * 4 + 2][arow] = av.z;
        As[ak4 * 4 + 3][arow] = av.w;
        float4 bv = *(const float4*)(Bw + (size_t)(k0 + bk) * N + n0 + bn4 * 4);
        *(float4*)&Bs[bk][bn4 * 4] = bv;
        __syncthreads();
#pragma unroll
        for (int k = 0; k < 16; k++) {
            float4 aa = *(const float4*)&As[k][tm];
            float4 bb = *(const float4*)&Bs[k][tn];
            float a4[4] = {aa.x, aa.y, aa.z, aa.w};
            float b4[4] = {bb.x, bb.y, bb.z, bb.w};
#pragma unroll
            for (int i = 0; i < 4; i++)
#pragma unroll
                for (int j = 0; j < 4; j++)
                    acc[i][j] = fmaf(a4[i], b4[j], acc[i][j]);
        }
    }
    float4 bv = *(const float4*)(bias + n0 + tn);
    float bias4[4] = {bv.x, bv.y, bv.z, bv.w};
#pragma unroll
    for (int i = 0; i < 4; i++) {
        size_t base = (size_t)(m0 + tm + i) * N + n0 + tn;
        float4 ov;
        ov.x = fmaxf(acc[i][0] + bias4[0], 0.f);
        ov.y = fmaxf(acc[i][1] + bias4[1], 0.f);
        ov.z = fmaxf(acc[i][2] + bias4[2], 0.f);
        ov.w = fmaxf(acc[i][3] + bias4[3], 0.f);
        *(float4*)(C + base) = ov;
    }
}

// ---------------------------------------------------------------------------
// FP16 tensor-core GEMM, 3-stage cp.async pipeline, ldmatrix fragments.
// Tile (MT*32)x128, BK=32, 256 threads. Warp tile (MT*16)x32.
// OUT_QKV: half out with Q columns (col<256) pre-scaled by 1/sqrt(dk)*log2e.
// ---------------------------------------------------------------------------
enum { OUT_HALF = 0, OUT_GELU = 1, OUT_RES = 2, OUT_QKV = 3 };

template <int OUT, int MT>
__global__ __launch_bounds__(256, 2) void gemm_fp16(const __half* __restrict__ A,
                                                    const __half* __restrict__ WT,
                                                    const float* __restrict__ bias,
                                                    const float* res,
                                                    float* C,
                                                    __half* hout,
                                                    int M, int N, int K) {
    extern __shared__ __half dsm[];
    constexpr int ASTG = MT * 32 * 40;   // halfs per A stage
    constexpr int BSTG = 128 * 40;       // halfs per B stage
    constexpr int STG  = ASTG + BSTG;

    int m0 = blockIdx.y * (MT * 32), n0 = blockIdx.x * 128;
    int tid = threadIdx.x, warp = tid >> 5, lane = tid & 31;
    int tq = lane >> 2, tc = lane & 3;
    int mb = (warp >> 2) * (MT * 16), nb = (warp & 3) * 32;

    int aR = mb + (lane & 15);
    int aC = (lane >> 4) * 8;
    int bR = nb + ((lane >> 4) & 1) * 8 + (lane & 7);
    int bC = ((lane >> 3) & 1) * 8;

    auto issue = [&](int s, int it) {
        int k0 = it * 32;
        // A: MT*128 16B chunks (row = c>>2, seg = (c&3)*8)
#pragma unroll
        for (int c = tid; c < MT * 128; c += 256) {
            int row = c >> 2, seg = (c & 3) * 8;
            cpa16(dsm + s * STG + row * 40 + seg,
                  A + (size_t)(m0 + row) * K + k0 + seg);
        }
        // B: 512 16B chunks
#pragma unroll
        for (int c = tid; c < 512; c += 256) {
            int row = c >> 2, seg = (c & 3) * 8;
            cpa16(dsm + s * STG + ASTG + row * 40 + seg,
                  WT + (size_t)(n0 + row) * K + k0 + seg);
        }
        asm volatile("cp.async.commit_group;");
    };

    float acc[MT][4][4] = {};
    int KT = K / 32;

    issue(0, 0);
    issue(1, 1);

    for (int it = 0; it < KT; ++it) {
        if (it < KT - 1) asm volatile("cp.async.wait_group 1;");
        else             asm volatile("cp.async.wait_group 0;");
        __syncthreads();
        if (it + 2 < KT) issue((it + 2) % 3, it + 2);

        const __half* A_s = dsm + (it % 3) * STG;
        const __half* B_s = A_s + ASTG;
#pragma unroll
        for (int ks = 0; ks < 2; ks++) {
            int kk = ks * 16;
            unsigned a[MT][4], b[4][2];
#pragma unroll
            for (int mt = 0; mt < MT; mt++)
                ldsm4(a[mt][0], a[mt][1], a[mt][2], a[mt][3],
                      smaddr(A_s + (aR + 16 * mt) * 40 + kk + aC));
#pragma unroll
            for (int p = 0; p < 2; p++)
                ldsm4(b[2 * p][0], b[2 * p][1], b[2 * p + 1][0], b[2 * p + 1][1],
                      smaddr(B_s + (bR + 16 * p) * 40 + kk + bC));
#pragma unroll
            for (int mt = 0; mt < MT; mt++)
#pragma unroll
                for (int nt = 0; nt < 4; nt++)
                    mma_f16(acc[mt][nt], a[mt][0], a[mt][1], a[mt][2], a[mt][3],
                            b[nt][0], b[nt][1]);
        }
    }

#pragma unroll
    for (int mt = 0; mt < MT; mt++) {
#pragma unroll
        for (int nt = 0; nt < 4; nt++) {
            int col = n0 + nb + 8 * nt + 2 * tc;
            float2 bb = *(const float2*)(bias + col);
#pragma unroll
            for (int hh = 0; hh < 2; hh++) {
                int row = m0 + mb + 16 * mt + tq + hh * 8;
                float u0 = acc[mt][nt][hh * 2 + 0] + bb.x;
                float u1 = acc[mt][nt][hh * 2 + 1] + bb.y;
                if (OUT == OUT_GELU) {
                    u0 = 0.5f * u0 * (1.0f + erff(u0 * 0.70710678118654752f));
                    u1 = 0.5f * u1 * (1.0f + erff(u1 * 0.70710678118654752f));
                }
                if (OUT == OUT_QKV && col < 256) {
                    u0 *= SCALE2F;
                    u1 *= SCALE2F;
                }
                if (OUT == OUT_RES) {
                    size_t base = (size_t)row * N + col;
                    float2 rr = *(const float2*)(res + base);
                    float2 ov = {u0 + rr.x, u1 + rr.y};
                    *(float2*)(C + base) = ov;
                } else {
                    *(__half2*)(hout + (size_t)row * N + col) = __floats2half2_rn(u0, u1);
                }
            }
        }
    }
}

// ---------------------------------------------------------------------------
// Importance scores
// ---------------------------------------------------------------------------
__global__ void score_kernel(const float* __restrict__ h,
                             const float* __restrict__ w2,
                             const float* __restrict__ b2,
                             float* __restrict__ scores) {
    int t = blockIdx.x * 8 + (threadIdx.x >> 5);
    int lane = threadIdx.x & 31;
    const float* hp = h + (size_t)t * DMODEL;
    float s = 0.f;
#pragma unroll
    for (int i = 0; i < 8; i++) s = fmaf(hp[lane + 32 * i], w2[lane + 32 * i], s);
#pragma unroll
    for (int o = 16; o > 0; o >>= 1) s += __shfl_xor_sync(0xffffffffu, s, o);
    if (lane == 0) scores[t] = 1.0f / (1.0f + __expf(-(s + b2[0])));
}

// ---------------------------------------------------------------------------
// Bottom-k mask + compaction
// ---------------------------------------------------------------------------
__global__ void mask_kernel(const float* __restrict__ scores, int* __restrict__ mask) {
    int t = blockIdx.x * 8 + (threadIdx.x >> 5);
    int lane = threadIdx.x & 31;
    int b = t / NTOK, i = t % NTOK;
    const float* sb = scores + b * NTOK;
    float si = sb[i];
    int cnt = 0;
#pragma unroll 4
    for (int j = lane; j < NTOK; j += 32) {
        float sj = sb[j];
        cnt += (sj < si) || (sj == si && j < i);
    }
#pragma unroll
    for (int o = 16; o > 0; o >>= 1) cnt += __shfl_xor_sync(0xffffffffu, cnt, o);
    if (lane == 0) mask[t] = (cnt < KDROP) ? 1 : 0;
}

__global__ void compact_kernel(const int* __restrict__ mask, int* __restrict__ idx) {
    int b = blockIdx.x, tid = threadIdx.x;
    int lane = tid & 31, w = tid >> 5;
    const int* mb = mask + b * NTOK;
    int base = tid * 9;
    int keep[9], cnt = 0;
#pragma unroll
    for (int i = 0; i < 9; i++) {
        keep[i] = (mb[base + i] == 0);
        cnt += keep[i];
    }
    int inc = cnt;
#pragma unroll
    for (int o = 1; o < 32; o <<= 1) {
        int n = __shfl_up_sync(0xffffffffu, inc, o);
        if (lane >= o) inc += n;
    }
    __shared__ int wsum[8];
    if (lane == 31) wsum[w] = inc;
    __syncthreads();
    int woff = 0;
    for (int j = 0; j < w; j++) woff += wsum[j];
    int off = woff + inc - cnt;
    int* ob = idx + b * NPAD;
#pragma unroll
    for (int i = 0; i < 9; i++)
        if (keep[i]) ob[off++] = base + i;
    if (tid < NPAD - NKEEP) ob[NKEEP + tid] = 0;
}

// ---------------------------------------------------------------------------
// FP16 flash attention, 256-query tile, double-buffered async K/V (R12 core).
// Max-free softmax, half2 exp2, ldmatrix frags, V via ldmatrix.trans.
// 256 threads: warp owns 32 q-rows (2 x 16-row groups).
// ---------------------------------------------------------------------------
__global__ __launch_bounds__(256, 2) void attn_fp16(const __half* __restrict__ qkv,
                                                    const int* __restrict__ idx,
                                                    __half* __restrict__ out) {
    __shared__ __half Ks[2][64][40];
    __shared__ __half Vs[2][64][40];
    __shared__ int    sidx[NPAD];

    int b = blockIdx.z, h = blockIdx.y;
    int q0 = blockIdx.x * 256;
    int tid = threadIdx.x;
    int w = tid >> 5, lane = tid & 31;
    int tq = lane >> 2, tc = lane & 3;
    int hoff = h * DK;

    int bR = ((lane >> 4) & 1) * 8 + (lane & 7);
    int bC = ((lane >> 3) & 1) * 8;
    int vR = lane & 15;
    int vC = (lane >> 4) * 8;

    const __half* qb = qkv + (size_t)b * NTOK * 768;

    for (int j = tid; j < NPAD; j += 256) sidx[j] = idx[b * NPAD + j];

    // Q fragments for both 16-row groups
    unsigned qa[2][2][4];
#pragma unroll
    for (int g = 0; g < 2; g++) {
        int rg = q0 + w * 32 + g * 16 + tq;
#pragma unroll
        for (int ks = 0; ks < 2; ks++) {
            int col = hoff + ks * 16 + 2 * tc;
            qa[g][ks][0] = *(const unsigned*)(qb + (size_t)rg * 768 + col);
            qa[g][ks][1] = *(const unsigned*)(qb + (size_t)(rg + 8) * 768 + col);
            qa[g][ks][2] = *(const unsigned*)(qb + (size_t)rg * 768 + col + 8);
            qa[g][ks][3] = *(const unsigned*)(qb + (size_t)(rg + 8) * 768 + col + 8);
        }
    }
    __syncthreads();   // sidx ready

    int krow = tid >> 2, kseg = tid & 3;
    auto issue = [&](int buf, int c0) {
        int t = sidx[c0 + krow];
        const __half* base = qb + (size_t)t * 768 + hoff + kseg * 8;
        cpa16(&Ks[buf][krow][kseg * 8], base + 256);
        cpa16(&Vs[buf][krow][kseg * 8], base + 512);
        asm volatile("cp.async.commit_group;");
    };

    issue(0, 0);

    float lsum[4] = {0.f, 0.f, 0.f, 0.f};
    float oacc[2][4][4] = {};
    const int NCH = NPAD / 64;

    for (int ci = 0; ci < NCH; ci++) {
        int buf = ci & 1;
        asm volatile("cp.async.wait_group 0;");
        __syncthreads();
        if (ci + 1 < NCH) issue(buf ^ 1, (ci + 1) * 64);

        unsigned pe[2][8], po[2][8];
#pragma unroll
        for (int g = 0; g < 2; g++) {
            float sacc[8][4] = {};
#pragma unroll
            for (int ks = 0; ks < 2; ks++) {
                int kk = ks * 16;
                unsigned kb[8][2];
#pragma unroll
                for (int p = 0; p < 4; p++)
                    ldsm4(kb[2 * p][0], kb[2 * p][1], kb[2 * p + 1][0], kb[2 * p + 1][1],
                          smaddr(&Ks[buf][bR + 16 * p][kk + bC]));
#pragma unroll
                for (int nt = 0; nt < 8; nt++)
                    mma_f16(sacc[nt], qa[g][ks][0], qa[g][ks][1], qa[g][ks][2],
                            qa[g][ks][3], kb[nt][0], kb[nt][1]);
            }

            if (ci == NCH - 1) {
                int c0 = ci * 64;
#pragma unroll
                for (int nt = 0; nt < 8; nt++) {
                    int jj = c0 + 8 * nt + 2 * tc;
                    if (jj >= NKEEP)     { sacc[nt][0] = -126.f; sacc[nt][2] = -126.f; }
                    if (jj + 1 >= NKEEP) { sacc[nt][1] = -126.f; sacc[nt][3] = -126.f; }
                }
            }

            __half2 lh0 = __float2half2_rn(0.f), lh1 = __float2half2_rn(0.f);
#pragma unroll
            for (int nt = 0; nt < 8; nt++) {
                pe[g][nt] = h2ex2(packh2(sacc[nt][0], sacc[nt][1]));
                po[g][nt] = h2ex2(packh2(sacc[nt][2], sacc[nt][3]));
                lh0 = __hadd2(lh0, *(__half2*)&pe[g][nt]);
                lh1 = __hadd2(lh1, *(__half2*)&po[g][nt]);
            }
            float2 lf0 = __half22float2(lh0);
            float2 lf1 = __half22float2(lh1);
            lsum[2 * g + 0] += lf0.x + lf0.y;
            lsum[2 * g + 1] += lf1.x + lf1.y;
        }

        // O += P V : V fragments loaded once, reused by both q-groups
#pragma unroll
        for (int ks2 = 0; ks2 < 4; ks2++) {
            int kk = ks2 * 16;
            unsigned vb[4][2];
#pragma unroll
            for (int p = 0; p < 2; p++)
                ldsm4t(vb[2 * p][0], vb[2 * p][1], vb[2 * p + 1][0], vb[2 * p + 1][1],
                       smaddr(&Vs[buf][kk + vR][16 * p + vC]));
#pragma unroll
            for (int nt = 0; nt < 4; nt++) {
                mma_f16(oacc[0][nt], pe[0][2 * ks2], po[0][2 * ks2],
                        pe[0][2 * ks2 + 1], po[0][2 * ks2 + 1], vb[nt][0], vb[nt][1]);
                mma_f16(oacc[1][nt], pe[1][2 * ks2], po[1][2 * ks2],
                        pe[1][2 * ks2 + 1], po[1][2 * ks2 + 1], vb[nt][0], vb[nt][1]);
            }
        }
    }

#pragma unroll
    for (int i = 0; i < 4; i++) {
        lsum[i] += __shfl_xor_sync(0xffffffffu, lsum[i], 1);
        lsum[i] += __shfl_xor_sync(0xffffffffu, lsum[i], 2);
    }

#pragma unroll
    for (int g = 0; g < 2; g++) {
        float inv0 = 1.0f / lsum[2 * g + 0], inv1 = 1.0f / lsum[2 * g + 1];
        int r0 = b * NTOK + q0 + w * 32 + g * 16 + tq;
#pragma unroll
        for (int nt = 0; nt < 4; nt++) {
            int col = hoff + 8 * nt + 2 * tc;
            *(__half2*)(out + (size_t)r0 * DMODEL + col) =
                __floats2half2_rn(oacc[g][nt][0] * inv0, oacc[g][nt][1] * inv0);
            *(__half2*)(out + (size_t)(r0 + 8) * DMODEL + col) =
                __floats2half2_rn(oacc[g][nt][2] * inv1, oacc[g][nt][3] * inv1);
        }
    }
}

// ---------------------------------------------------------------------------
// Final LN + mean
// ---------------------------------------------------------------------------
__global__ void mean1_kernel(const float* __restrict__ x, const float2* __restrict__ st,
                             float* __restrict__ part) {
    int b = blockIdx.y, ch = blockIdx.x, d = threadIdx.x;
    const float* p = x + ((size_t)b * NTOK + ch * 64) * DMODEL + d;
    const float2* sp = st + b * NTOK + ch * 64;
    float s = 0.f;
#pragma unroll 8
    for (int n = 0; n < 64; n++) {
        float2 ms = sp[n];
        s += (p[(size_t)n * DMODEL] - ms.x) * ms.y;
    }
    part[((size_t)b * NCHUNK + ch) * DMODEL + d] = s;
}

__global__ void mean2_kernel(const float* __restrict__ part,
                             const float* __restrict__ g,
                             const float* __restrict__ bo,
                             float* __restrict__ out) {
    int b = blockIdx.x, d = threadIdx.x;
    float s = 0.f;
    for (int c = 0; c < NCHUNK; c++) s += part[((size_t)b * NCHUNK + c) * DMODEL + d];
    out[b * DMODEL + d] = s * (1.0f / NTOK) * g[d] + bo[d];
}

// ---------------------------------------------------------------------------
// Launcher
// ---------------------------------------------------------------------------
extern "C" void kernel_launch(void* const* d_in, const int* in_sizes, int n_in,
                              void* d_out, int out_size) {
    const float* x       = (const float*)d_in[0];
    const float* patch_w = (const float*)d_in[1];
    const float* patch_b = (const float*)d_in[2];
    const float* pos     = (const float*)d_in[3];
    const float* imp_w1  = (const float*)d_in[4];
    const float* imp_b1  = (const float*)d_in[5];
    const float* imp_w2  = (const float*)d_in[6];
    const float* imp_b2  = (const float*)d_in[7];
    const float* ln1_g   = (const float*)d_in[8];
    const float* ln1_b   = (const float*)d_in[9];
    const float* qkv_w   = (const float*)d_in[10];
    const float* qkv_b   = (const float*)d_in[11];
    const float* proj_w  = (const float*)d_in[12];
    const float* proj_b  = (const float*)d_in[13];
    const float* ln2_g   = (const float*)d_in[14];
    const float* ln2_b   = (const float*)d_in[15];
    const float* mlp_w1  = (const float*)d_in[16];
    const float* mlp_b1  = (const float*)d_in[17];
    const float* mlp_w2  = (const float*)d_in[18];
    const float* mlp_b2  = (const float*)d_in[19];
    const float* out_g   = (const float*)d_in[20];
    const float* out_b   = (const float*)d_in[21];
    float* out = (float*)d_out;

    float *tokens, *hbuf, *scores, *part;
    __half *hln, *qkv, *attn, *mlp, *wt;
    float2* stats;
    int *mask, *idx;
    cudaGetSymbolAddress((void**)&tokens, g_tokens);
    cudaGetSymbolAddress((void**)&hbuf,   g_h);
    cudaGetSymbolAddress((void**)&hln,    g_hln);
    cudaGetSymbolAddress((void**)&qkv,    g_qkv);
    cudaGetSymbolAddress((void**)&attn,   g_attn);
    cudaGetSymbolAddress((void**)&mlp,    g_mlp);
    cudaGetSymbolAddress((void**)&scores, g_scores);
    cudaGetSymbolAddress((void**)&mask,   g_mask);
    cudaGetSymbolAddress((void**)&idx,    g_idx);
    cudaGetSymbolAddress((void**)&part,   g_part);
    cudaGetSymbolAddress((void**)&stats,  g_stats);
    cudaGetSymbolAddress((void**)&wt,     g_wt);

    cudaFuncSetAttribute((const void*)gemm_fp16<OUT_QKV, 3>,
                         cudaFuncAttributeMaxDynamicSharedMemorySize, GEMM_SMEM(3));
    cudaFuncSetAttribute((const void*)gemm_fp16<OUT_GELU, 4>,
                         cudaFuncAttributeMaxDynamicSharedMemorySize, GEMM_SMEM(4));
    cudaFuncSetAttribute((const void*)gemm_fp16<OUT_RES, 2>,
                         cudaFuncAttributeMaxDynamicSharedMemorySize, GEMM_SMEM(2));

    dim3 tb(32, 8);

    transpose_w<<<dim3(24, 8, 3), tb>>>(qkv_w, wt + OFF_QKV, DMODEL, 768);              // 0
    patch_kernel<<<MTOT, 256>>>(x, patch_w, patch_b, pos, tokens);                       // 1
    ln_half_kernel<<<MTOT / 8, 256>>>(tokens, ln1_g, ln1_b, hln);                        // 2
    gemm_fp16<OUT_QKV, 3><<<dim3(6, 96), 256, GEMM_SMEM(3)>>>(
        hln, wt + OFF_QKV, qkv_b, nullptr, nullptr, qkv, MTOT, 768, DMODEL);             // 3 (profiled)
    transpose_w<<<dim3(8, 8, 3), tb>>>(proj_w, wt + OFF_PROJ, DMODEL, DMODEL);           // 4
    transpose_w<<<dim3(32, 8, 3), tb>>>(mlp_w1, wt + OFF_MLP1, DMODEL, 1024);            // 5
    transpose_w<<<dim3(8, 32, 3), tb>>>(mlp_w2, wt + OFF_MLP2, 1024, DMODEL);            // 6
    gemm_f32_relu<<<dim3(DMODEL / 64, MTOT / 64), 256>>>(tokens, imp_w1, imp_b1,
                                                         hbuf, MTOT, DMODEL, DMODEL);    // 7
    score_kernel<<<MTOT / 8, 256>>>(hbuf, imp_w2, imp_b2, scores);                       // 8
    mask_kernel<<<MTOT / 8, 256>>>(scores, mask);                                        // 9
    compact_kernel<<<BATCH, 256>>>(mask, idx);                                           // 10

    for (int l = 0; l < DEPTH; l++) {
        if (l > 0) {
            ln_half_kernel<<<MTOT / 8, 256>>>(tokens, ln1_g + l * DMODEL,
                                              ln1_b + l * DMODEL, hln);
            gemm_fp16<OUT_QKV, 3><<<dim3(6, 96), 256, GEMM_SMEM(3)>>>(
                hln, wt + OFF_QKV + (size_t)l * DMODEL * 768, qkv_b + l * 768,
                nullptr, nullptr, qkv, MTOT, 768, DMODEL);
        }
        attn_fp16<<<dim3(NTOK / 256, NHEADS, BATCH), 256>>>(qkv, idx, attn);
        gemm_fp16<OUT_RES, 2><<<dim3(2, 144), 256, GEMM_SMEM(2)>>>(
            attn, wt + OFF_PROJ + (size_t)l * DMODEL * DMODEL, proj_b + l * DMODEL,
            tokens, tokens, nullptr, MTOT, DMODEL, DMODEL);
        ln_half_kernel<<<MTOT / 8, 256>>>(tokens, ln2_g + l * DMODEL,
                                          ln2_b + l * DMODEL, hln);
        gemm_fp16<OUT_GELU, 4><<<dim3(8, 72), 256, GEMM_SMEM(4)>>>(
            hln, wt + OFF_MLP1 + (size_t)l * DMODEL * 1024, mlp_b1 + l * 1024,
            nullptr, nullptr, mlp, MTOT, 1024, DMODEL);
        gemm_fp16<OUT_RES, 2><<<dim3(2, 144), 256, GEMM_SMEM(2)>>>(
            mlp, wt + OFF_MLP2 + (size_t)l * 1024 * DMODEL, mlp_b2 + l * DMODEL,
            tokens, tokens, nullptr, MTOT, DMODEL, 1024);
    }

    ln_stats_kernel<<<MTOT / 8, 256>>>(tokens, stats);
    mean1_kernel<<<dim3(NCHUNK, BATCH), 256>>>(tokens, stats, part);
    mean2_kernel<<<BATCH, 256>>>(part, out_g, out_b, out);
}

// round 15
// speedup vs baseline: 1.0697x; 1.0011x over previous
#include <cuda_runtime.h>
#include <cuda_fp16.h>
#include <math.h>

// ---------------------------------------------------------------------------
#define BATCH   4
#define NTOK    2304
#define DMODEL  256
#define NHEADS  8
#define DK      32
#define DEPTH   3
#define KDROP   345
#define NKEEP   (NTOK - KDROP)     // 1959
#define NPAD    1984               // 31 * 64
#define MTOT    (BATCH * NTOK)     // 9216
#define NCHUNK  36

// weight scratch offsets (halfs), transposed [N][K] layout
#define OFF_QKV  0
#define OFF_PROJ 589824
#define OFF_MLP1 786432
#define OFF_MLP2 1572864
#define WTOT     2359296

// GEMM 3-stage pipeline smem (bytes): stage = A(MT*32 x 40) + B(128 x 40) halfs
#define GEMM_SMEM(MT) (((MT) * 32 * 40 + 128 * 40) * 3 * 2)

// 1/sqrt(32) * log2(e), folded into Q at the QKV epilogue
#define SCALE2F 0.2550660030f

// ---------------------------------------------------------------------------
__device__ float  g_tokens[MTOT * DMODEL];
__device__ float  g_h     [MTOT * DMODEL];
__device__ __half g_hln   [MTOT * DMODEL];
__device__ __half g_qkv   [MTOT * 768];
__device__ __half g_attn  [MTOT * DMODEL];
__device__ __half g_mlp   [MTOT * 1024];
__device__ float  g_scores[MTOT];
__device__ int    g_mask  [MTOT];
__device__ int    g_idx   [BATCH * NPAD];
__device__ float  g_part  [BATCH * NCHUNK * DMODEL];
__device__ float2 g_stats [MTOT];
__device__ __half g_wt    [WTOT];

// ---------------------------------------------------------------------------
__device__ __forceinline__ unsigned packh2(float a, float b) {
    __half2 h = __floats2half2_rn(a, b);
    return *(unsigned*)&h;
}

__device__ __forceinline__ unsigned h2ex2(unsigned x) {
    unsigned r;
    asm("ex2.approx.f16x2 %0, %1;" : "=r"(r) : "r"(x));
    return r;
}

__device__ __forceinline__ void mma_f16(float c[4],
                                        unsigned a0, unsigned a1, unsigned a2, unsigned a3,
                                        unsigned b0, unsigned b1) {
    asm volatile(
        "mma.sync.aligned.m16n8k16.row.col.f32.f16.f16.f32 "
        "{%0,%1,%2,%3}, {%4,%5,%6,%7}, {%8,%9}, {%0,%1,%2,%3};"
        : "+f"(c[0]), "+f"(c[1]), "+f"(c[2]), "+f"(c[3])
        : "r"(a0), "r"(a1), "r"(a2), "r"(a3), "r"(b0), "r"(b1));
}

__device__ __forceinline__ void cpa16(void* smem, const void* g) {
    unsigned s = (unsigned)__cvta_generic_to_shared(smem);
    asm volatile("cp.async.ca.shared.global [%0], [%1], 16;" :: "r"(s), "l"(g));
}

__device__ __forceinline__ unsigned smaddr(const void* p) {
    return (unsigned)__cvta_generic_to_shared(p);
}

__device__ __forceinline__ void ldsm4(unsigned& r0, unsigned& r1, unsigned& r2, unsigned& r3,
                                      unsigned a) {
    asm volatile("ldmatrix.sync.aligned.m8n8.x4.shared.b16 {%0,%1,%2,%3}, [%4];"
                 : "=r"(r0), "=r"(r1), "=r"(r2), "=r"(r3) : "r"(a));
}

__device__ __forceinline__ void ldsm4t(unsigned& r0, unsigned& r1, unsigned& r2, unsigned& r3,
                                       unsigned a) {
    asm volatile("ldmatrix.sync.aligned.m8n8.x4.trans.shared.b16 {%0,%1,%2,%3}, [%4];"
                 : "=r"(r0), "=r"(r1), "=r"(r2), "=r"(r3) : "r"(a));
}

// ---------------------------------------------------------------------------
// Tiled transpose + f32->f16: W[L][K][N] -> WT[L][N][K] half
// ---------------------------------------------------------------------------
__global__ void transpose_w(const float* __restrict__ W, __half* __restrict__ WT,
                            int K, int N) {
    __shared__ float t[32][33];
    int n0 = blockIdx.x * 32, k0 = blockIdx.y * 32;
    int l = blockIdx.z;
    W  += (size_t)l * K * N;
    WT += (size_t)l * K * N;
    int tx = threadIdx.x, ty = threadIdx.y;
#pragma unroll
    for (int r = 0; r < 4; r++)
        t[ty + 8 * r][tx] = W[(size_t)(k0 + ty + 8 * r) * N + n0 + tx];
    __syncthreads();
#pragma unroll
    for (int r = 0; r < 4; r++)
        WT[(size_t)(n0 + ty + 8 * r) * K + k0 + tx] = __float2half(t[tx][ty + 8 * r]);
}

// ---------------------------------------------------------------------------
// Patch embed
// ---------------------------------------------------------------------------
__global__ void patch_kernel(const float* __restrict__ x,
                             const float* __restrict__ pw,
                             const float* __restrict__ pb,
                             const float* __restrict__ pos,
                             float* __restrict__ tokens) {
    int t = blockIdx.x;
    int b = t / NTOK, n = t % NTOK;
    int hc = n / 48, wc = n % 48;
    __shared__ float xs[12];
    if (threadIdx.x < 12) {
        int c = threadIdx.x / 4, pq = threadIdx.x % 4;
        int p = pq / 2, q = pq % 2;
        xs[threadIdx.x] = x[(((size_t)b * 3 + c) * 96 + (hc * 2 + p)) * 96 + (wc * 2 + q)];
    }
    __syncthreads();
    int d = threadIdx.x;
    float acc = pb[d];
#pragma unroll
    for (int e = 0; e < 12; e++) acc = fmaf(xs[e], pw[d * 12 + e], acc);
    tokens[(size_t)t * DMODEL + d] = acc + pos[(size_t)n * DMODEL + d];
}

// ---------------------------------------------------------------------------
// LayerNorm -> half output
// ---------------------------------------------------------------------------
__global__ void ln_half_kernel(const float* __restrict__ x,
                               const float* __restrict__ g,
                               const float* __restrict__ bta,
                               __half* __restrict__ y) {
    int t = blockIdx.x * 8 + (threadIdx.x >> 5);
    int lane = threadIdx.x & 31;
    const float* xp = x + (size_t)t * DMODEL + 8 * lane;
    float4 v0 = *(const float4*)xp;
    float4 v1 = *(const float4*)(xp + 4);
    float s = v0.x + v0.y + v0.z + v0.w + v1.x + v1.y + v1.z + v1.w;
#pragma unroll
    for (int o = 16; o > 0; o >>= 1) s += __shfl_xor_sync(0xffffffffu, s, o);
    float m = s * (1.0f / DMODEL);
    float vs = 0.f;
    float vv[8] = {v0.x, v0.y, v0.z, v0.w, v1.x, v1.y, v1.z, v1.w};
#pragma unroll
    for (int i = 0; i < 8; i++) { float d = vv[i] - m; vs = fmaf(d, d, vs); }
#pragma unroll
    for (int o = 16; o > 0; o >>= 1) vs += __shfl_xor_sync(0xffffffffu, vs, o);
    float rs = rsqrtf(vs * (1.0f / DMODEL) + 1e-5f);
    const float* gp = g + 8 * lane;
    const float* bp = bta + 8 * lane;
    __half2* yp = (__half2*)(y + (size_t)t * DMODEL + 8 * lane);
#pragma unroll
    for (int i = 0; i < 4; i++) {
        float g0 = gp[2 * i], g1 = gp[2 * i + 1];
        float b0 = bp[2 * i], b1 = bp[2 * i + 1];
        yp[i] = __floats2half2_rn((vv[2 * i] - m) * rs * g0 + b0,
                                  (vv[2 * i + 1] - m) * rs * g1 + b1);
    }
}

// ---------------------------------------------------------------------------
// LN stats (final LN only)
// ---------------------------------------------------------------------------
__global__ void ln_stats_kernel(const float* __restrict__ x, float2* __restrict__ st) {
    int t = blockIdx.x * 8 + (threadIdx.x >> 5);
    int lane = threadIdx.x & 31;
    const float* xp = x + (size_t)t * DMODEL;
    float v[8];
    float s = 0.f;
#pragma unroll
    for (int i = 0; i < 8; i++) { v[i] = xp[lane + 32 * i]; s += v[i]; }
#pragma unroll
    for (int o = 16; o > 0; o >>= 1) s += __shfl_xor_sync(0xffffffffu, s, o);
    float m = s * (1.0f / DMODEL);
    float vs = 0.f;
#pragma unroll
    for (int i = 0; i < 8; i++) { float d = v[i] - m; vs = fmaf(d, d, vs); }
#pragma unroll
    for (int o = 16; o > 0; o >>= 1) vs += __shfl_xor_sync(0xffffffffu, vs, o);
    float rs = rsqrtf(vs * (1.0f / DMODEL) + 1e-5f);
    if (lane == 0) { float2 o2 = {m, rs}; st[t] = o2; }
}

// ---------------------------------------------------------------------------
// fp32 FFMA GEMM + relu (importance path only: exact)
// ---------------------------------------------------------------------------
__global__ void gemm_f32_relu(const float* __restrict__ A,
                              const float* __restrict__ Bw,
                              const float* __restrict__ bias,
                              float* __restrict__ C,
                              int M, int N, int K) {
    __shared__ float As[16][68];
    __shared__ float Bs[16][68];
    int m0 = blockIdx.y * 64, n0 = blockIdx.x * 64;
    int tid = threadIdx.x;
    int tm = (tid >> 4) * 4, tn = (tid & 15) * 4;
    int arow = tid >> 2, ak4 = tid & 3;
    int bk = tid >> 4, bn4 = tid & 15;

    float acc[4][4] = {};
    for (int k0 = 0; k0 < K; k0 += 16) {
        __syncthreads();
        float4 av = *(const float4*)(A + (size_t)(m0 + arow) * K + k0 + ak4 * 4);
        As[ak4 * 4 + 0][arow] = av.x;
        As[ak4 * 4 + 1][arow] = av.y;
        As[ak4 * 4 + 2][arow] = av.z;
        As[ak4 * 4 + 3][arow] = av.w;
        float4 bv = *(const float4*)(Bw + (size_t)(k0 + bk) * N + n0 + bn4 * 4);
        *(float4*)&Bs[bk][bn4 * 4] = bv;
        __syncthreads();
#pragma unroll
        for (int k = 0; k < 16; k++) {
            float4 aa = *(const float4*)&As[k][tm];
            float4 bb = *(const float4*)&Bs[k][tn];
            float a4[4] = {aa.x, aa.y, aa.z, aa.w};
            float b4[4] = {bb.x, bb.y, bb.z, bb.w};
#pragma unroll
            for (int i = 0; i < 4; i++)
#pragma unroll
                for (int j = 0; j < 4; j++)
                    acc[i][j] = fmaf(a4[i], b4[j], acc[i][j]);
        }
    }
    float4 bv = *(const float4*)(bias + n0 + tn);
    float bias4[4] = {bv.x, bv.y, bv.z, bv.w};
#pragma unroll
    for (int i = 0; i < 4; i++) {
        size_t base = (size_t)(m0 + tm + i) * N + n0 + tn;
        float4 ov;
        ov.x = fmaxf(acc[i][0] + bias4[0], 0.f);
        ov.y = fmaxf(acc[i][1] + bias4[1], 0.f);
        ov.z = fmaxf(acc[i][2] + bias4[2], 0.f);
        ov.w = fmaxf(acc[i][3] + bias4[3], 0.f);
        *(float4*)(C + base) = ov;
    }
}

// ---------------------------------------------------------------------------
// FP16 tensor-core GEMM, 3-stage cp.async pipeline, ldmatrix fragments.
// Tile (MT*32)x128, BK=32, 256 threads. Warp tile (MT*16)x32.
// OUT_QKV: half out with Q columns (col<256) pre-scaled by 1/sqrt(dk)*log2e.
// ---------------------------------------------------------------------------
enum { OUT_HALF = 0, OUT_GELU = 1, OUT_RES = 2, OUT_QKV = 3 };

template <int OUT, int MT>
__global__ __launch_bounds__(256, 2) void gemm_fp16(const __half* __restrict__ A,
                                                    const __half* __restrict__ WT,
                                                    const float* __restrict__ bias,
                                                    const float* res,
                                                    float* C,
                                                    __half* hout,
                                                    int M, int N, int K) {
    extern __shared__ __half dsm[];
    constexpr int ASTG = MT * 32 * 40;   // halfs per A stage
    constexpr int BSTG = 128 * 40;       // halfs per B stage
    constexpr int STG  = ASTG + BSTG;

    int m0 = blockIdx.y * (MT * 32), n0 = blockIdx.x * 128;
    int tid = threadIdx.x, warp = tid >> 5, lane = tid & 31;
    int tq = lane >> 2, tc = lane & 3;
    int mb = (warp >> 2) * (MT * 16), nb = (warp & 3) * 32;

    int aR = mb + (lane & 15);
    int aC = (lane >> 4) * 8;
    int bR = nb + ((lane >> 4) & 1) * 8 + (lane & 7);
    int bC = ((lane >> 3) & 1) * 8;

    auto issue = [&](int s, int it) {
        int k0 = it * 32;
#pragma unroll
        for (int c = tid; c < MT * 128; c += 256) {
            int row = c >> 2, seg = (c & 3) * 8;
            cpa16(dsm + s * STG + row * 40 + seg,
                  A + (size_t)(m0 + row) * K + k0 + seg);
        }
#pragma unroll
        for (int c = tid; c < 512; c += 256) {
            int row = c >> 2, seg = (c & 3) * 8;
            cpa16(dsm + s * STG + ASTG + row * 40 + seg,
                  WT + (size_t)(n0 + row) * K + k0 + seg);
        }
        asm volatile("cp.async.commit_group;");
    };

    float acc[MT][4][4] = {};
    int KT = K / 32;

    issue(0, 0);
    issue(1, 1);

    for (int it = 0; it < KT; ++it) {
        if (it < KT - 1) asm volatile("cp.async.wait_group 1;");
        else             asm volatile("cp.async.wait_group 0;");
        __syncthreads();
        if (it + 2 < KT) issue((it + 2) % 3, it + 2);

        const __half* A_s = dsm + (it % 3) * STG;
        const __half* B_s = A_s + ASTG;
#pragma unroll
        for (int ks = 0; ks < 2; ks++) {
            int kk = ks * 16;
            unsigned a[MT][4], b[4][2];
#pragma unroll
            for (int mt = 0; mt < MT; mt++)
                ldsm4(a[mt][0], a[mt][1], a[mt][2], a[mt][3],
                      smaddr(A_s + (aR + 16 * mt) * 40 + kk + aC));
#pragma unroll
            for (int p = 0; p < 2; p++)
                ldsm4(b[2 * p][0], b[2 * p][1], b[2 * p + 1][0], b[2 * p + 1][1],
                      smaddr(B_s + (bR + 16 * p) * 40 + kk + bC));
#pragma unroll
            for (int mt = 0; mt < MT; mt++)
#pragma unroll
                for (int nt = 0; nt < 4; nt++)
                    mma_f16(acc[mt][nt], a[mt][0], a[mt][1], a[mt][2], a[mt][3],
                            b[nt][0], b[nt][1]);
        }
    }

#pragma unroll
    for (int mt = 0; mt < MT; mt++) {
#pragma unroll
        for (int nt = 0; nt < 4; nt++) {
            int col = n0 + nb + 8 * nt + 2 * tc;
            float2 bb = *(const float2*)(bias + col);
#pragma unroll
            for (int hh = 0; hh < 2; hh++) {
                int row = m0 + mb + 16 * mt + tq + hh * 8;
                float u0 = acc[mt][nt][hh * 2 + 0] + bb.x;
                float u1 = acc[mt][nt][hh * 2 + 1] + bb.y;
                if (OUT == OUT_GELU) {
                    u0 = 0.5f * u0 * (1.0f + erff(u0 * 0.70710678118654752f));
                    u1 = 0.5f * u1 * (1.0f + erff(u1 * 0.70710678118654752f));
                }
                if (OUT == OUT_QKV && col < 256) {
                    u0 *= SCALE2F;
                    u1 *= SCALE2F;
                }
                if (OUT == OUT_RES) {
                    size_t base = (size_t)row * N + col;
                    float2 rr = *(const float2*)(res + base);
                    float2 ov = {u0 + rr.x, u1 + rr.y};
                    *(float2*)(C + base) = ov;
                } else {
                    *(__half2*)(hout + (size_t)row * N + col) = __floats2half2_rn(u0, u1);
                }
            }
        }
    }
}

// ---------------------------------------------------------------------------
// Importance scores
// ---------------------------------------------------------------------------
__global__ void score_kernel(const float* __restrict__ h,
                             const float* __restrict__ w2,
                             const float* __restrict__ b2,
                             float* __restrict__ scores) {
    int t = blockIdx.x * 8 + (threadIdx.x >> 5);
    int lane = threadIdx.x & 31;
    const float* hp = h + (size_t)t * DMODEL;
    float s = 0.f;
#pragma unroll
    for (int i = 0; i < 8; i++) s = fmaf(hp[lane + 32 * i], w2[lane + 32 * i], s);
#pragma unroll
    for (int o = 16; o > 0; o >>= 1) s += __shfl_xor_sync(0xffffffffu, s, o);
    if (lane == 0) scores[t] = 1.0f / (1.0f + __expf(-(s + b2[0])));
}

// ---------------------------------------------------------------------------
// Bottom-k mask + compaction
// ---------------------------------------------------------------------------
__global__ void mask_kernel(const float* __restrict__ scores, int* __restrict__ mask) {
    int t = blockIdx.x * 8 + (threadIdx.x >> 5);
    int lane = threadIdx.x & 31;
    int b = t / NTOK, i = t % NTOK;
    const float* sb = scores + b * NTOK;
    float si = sb[i];
    int cnt = 0;
#pragma unroll 4
    for (int j = lane; j < NTOK; j += 32) {
        float sj = sb[j];
        cnt += (sj < si) || (sj == si && j < i);
    }
#pragma unroll
    for (int o = 16; o > 0; o >>= 1) cnt += __shfl_xor_sync(0xffffffffu, cnt, o);
    if (lane == 0) mask[t] = (cnt < KDROP) ? 1 : 0;
}

__global__ void compact_kernel(const int* __restrict__ mask, int* __restrict__ idx) {
    int b = blockIdx.x, tid = threadIdx.x;
    int lane = tid & 31, w = tid >> 5;
    const int* mb = mask + b * NTOK;
    int base = tid * 9;
    int keep[9], cnt = 0;
#pragma unroll
    for (int i = 0; i < 9; i++) {
        keep[i] = (mb[base + i] == 0);
        cnt += keep[i];
    }
    int inc = cnt;
#pragma unroll
    for (int o = 1; o < 32; o <<= 1) {
        int n = __shfl_up_sync(0xffffffffu, inc, o);
        if (lane >= o) inc += n;
    }
    __shared__ int wsum[8];
    if (lane == 31) wsum[w] = inc;
    __syncthreads();
    int woff = 0;
    for (int j = 0; j < w; j++) woff += wsum[j];
    int off = woff + inc - cnt;
    int* ob = idx + b * NPAD;
#pragma unroll
    for (int i = 0; i < 9; i++)
        if (keep[i]) ob[off++] = base + i;
    if (tid < NPAD - NKEEP) ob[NKEEP + tid] = 0;
}

// ---------------------------------------------------------------------------
// FP16 flash attention, 256-query tile, 3-stage async K/V ring (wait_group 1:
// each gather gets two compute-spans of latency cover).
// Max-free softmax, half2 exp2, ldmatrix frags, V via ldmatrix.trans.
// 256 threads: warp owns 32 q-rows (2 x 16-row groups).
// ---------------------------------------------------------------------------
__global__ __launch_bounds__(256, 2) void attn_fp16(const __half* __restrict__ qkv,
                                                    const int* __restrict__ idx,
                                                    __half* __restrict__ out) {
    __shared__ __half Ks[3][64][40];
    __shared__ __half Vs[3][64][40];
    __shared__ int    sidx[NPAD];

    int b = blockIdx.z, h = blockIdx.y;
    int q0 = blockIdx.x * 256;
    int tid = threadIdx.x;
    int w = tid >> 5, lane = tid & 31;
    int tq = lane >> 2, tc = lane & 3;
    int hoff = h * DK;

    int bR = ((lane >> 4) & 1) * 8 + (lane & 7);
    int bC = ((lane >> 3) & 1) * 8;
    int vR = lane & 15;
    int vC = (lane >> 4) * 8;

    const __half* qb = qkv + (size_t)b * NTOK * 768;

    for (int j = tid; j < NPAD; j += 256) sidx[j] = idx[b * NPAD + j];

    // Q fragments for both 16-row groups
    unsigned qa[2][2][4];
#pragma unroll
    for (int g = 0; g < 2; g++) {
        int rg = q0 + w * 32 + g * 16 + tq;
#pragma unroll
        for (int ks = 0; ks < 2; ks++) {
            int col = hoff + ks * 16 + 2 * tc;
            qa[g][ks][0] = *(const unsigned*)(qb + (size_t)rg * 768 + col);
            qa[g][ks][1] = *(const unsigned*)(qb + (size_t)(rg + 8) * 768 + col);
            qa[g][ks][2] = *(const unsigned*)(qb + (size_t)rg * 768 + col + 8);
            qa[g][ks][3] = *(const unsigned*)(qb + (size_t)(rg + 8) * 768 + col + 8);
        }
    }
    __syncthreads();   // sidx ready

    int krow = tid >> 2, kseg = tid & 3;
    auto issue = [&](int buf, int c0) {
        int t = sidx[c0 + krow];
        const __half* base = qb + (size_t)t * 768 + hoff + kseg * 8;
        cpa16(&Ks[buf][krow][kseg * 8], base + 256);
        cpa16(&Vs[buf][krow][kseg * 8], base + 512);
        asm volatile("cp.async.commit_group;");
    };

    const int NCH = NPAD / 64;
    issue(0, 0);
    issue(1, 64);

    float lsum[4] = {0.f, 0.f, 0.f, 0.f};
    float oacc[2][4][4] = {};

    for (int ci = 0; ci < NCH; ci++) {
        int buf = ci % 3;
        if (ci + 1 < NCH) asm volatile("cp.async.wait_group 1;");
        else              asm volatile("cp.async.wait_group 0;");
        __syncthreads();
        if (ci + 2 < NCH) issue((ci + 2) % 3, (ci + 2) * 64);

        unsigned pe[2][8], po[2][8];
#pragma unroll
        for (int g = 0; g < 2; g++) {
            float sacc[8][4] = {};
#pragma unroll
            for (int ks = 0; ks < 2; ks++) {
                int kk = ks * 16;
                unsigned kb[8][2];
#pragma unroll
                for (int p = 0; p < 4; p++)
                    ldsm4(kb[2 * p][0], kb[2 * p][1], kb[2 * p + 1][0], kb[2 * p + 1][1],
                          smaddr(&Ks[buf][bR + 16 * p][kk + bC]));
#pragma unroll
                for (int nt = 0; nt < 8; nt++)
                    mma_f16(sacc[nt], qa[g][ks][0], qa[g][ks][1], qa[g][ks][2],
                            qa[g][ks][3], kb[nt][0], kb[nt][1]);
            }

            if (ci == NCH - 1) {
                int c0 = ci * 64;
#pragma unroll
                for (int nt = 0; nt < 8; nt++) {
                    int jj = c0 + 8 * nt + 2 * tc;
                    if (jj >= NKEEP)     { sacc[nt][0] = -126.f; sacc[nt][2] = -126.f; }
                    if (jj + 1 >= NKEEP) { sacc[nt][1] = -126.f; sacc[nt][3] = -126.f; }
                }
            }

            __half2 lh0 = __float2half2_rn(0.f), lh1 = __float2half2_rn(0.f);
#pragma unroll
            for (int nt = 0; nt < 8; nt++) {
                pe[g][nt] = h2ex2(packh2(sacc[nt][0], sacc[nt][1]));
                po[g][nt] = h2ex2(packh2(sacc[nt][2], sacc[nt][3]));
                lh0 = __hadd2(lh0, *(__half2*)&pe[g][nt]);
                lh1 = __hadd2(lh1, *(__half2*)&po[g][nt]);
            }
            float2 lf0 = __half22float2(lh0);
            float2 lf1 = __half22float2(lh1);
            lsum[2 * g + 0] += lf0.x + lf0.y;
            lsum[2 * g + 1] += lf1.x + lf1.y;
        }

        // O += P V : V fragments loaded once, reused by both q-groups
#pragma unroll
        for (int ks2 = 0; ks2 < 4; ks2++) {
            int kk = ks2 * 16;
            unsigned vb[4][2];
#pragma unroll
            for (int p = 0; p < 2; p++)
                ldsm4t(vb[2 * p][0], vb[2 * p][1], vb[2 * p + 1][0], vb[2 * p + 1][1],
                       smaddr(&Vs[buf][kk + vR][16 * p + vC]));
#pragma unroll
            for (int nt = 0; nt < 4; nt++) {
                mma_f16(oacc[0][nt], pe[0][2 * ks2], po[0][2 * ks2],
                        pe[0][2 * ks2 + 1], po[0][2 * ks2 + 1], vb[nt][0], vb[nt][1]);
                mma_f16(oacc[1][nt], pe[1][2 * ks2], po[1][2 * ks2],
                        pe[1][2 * ks2 + 1], po[1][2 * ks2 + 1], vb[nt][0], vb[nt][1]);
            }
        }
    }

#pragma unroll
    for (int i = 0; i < 4; i++) {
        lsum[i] += __shfl_xor_sync(0xffffffffu, lsum[i], 1);
        lsum[i] += __shfl_xor_sync(0xffffffffu, lsum[i], 2);
    }

#pragma unroll
    for (int g = 0; g < 2; g++) {
        float inv0 = 1.0f / lsum[2 * g + 0], inv1 = 1.0f / lsum[2 * g + 1];
        int r0 = b * NTOK + q0 + w * 32 + g * 16 + tq;
#pragma unroll
        for (int nt = 0; nt < 4; nt++) {
            int col = hoff + 8 * nt + 2 * tc;
            *(__half2*)(out + (size_t)r0 * DMODEL + col) =
                __floats2half2_rn(oacc[g][nt][0] * inv0, oacc[g][nt][1] * inv0);
            *(__half2*)(out + (size_t)(r0 + 8) * DMODEL + col) =
                __floats2half2_rn(oacc[g][nt][2] * inv1, oacc[g][nt][3] * inv1);
        }
    }
}

// ---------------------------------------------------------------------------
// Final LN + mean
// ---------------------------------------------------------------------------
__global__ void mean1_kernel(const float* __restrict__ x, const float2* __restrict__ st,
                             float* __restrict__ part) {
    int b = blockIdx.y, ch = blockIdx.x, d = threadIdx.x;
    const float* p = x + ((size_t)b * NTOK + ch * 64) * DMODEL + d;
    const float2* sp = st + b * NTOK + ch * 64;
    float s = 0.f;
#pragma unroll 8
    for (int n = 0; n < 64; n++) {
        float2 ms = sp[n];
        s += (p[(size_t)n * DMODEL] - ms.x) * ms.y;
    }
    part[((size_t)b * NCHUNK + ch) * DMODEL + d] = s;
}

__global__ void mean2_kernel(const float* __restrict__ part,
                             const float* __restrict__ g,
                             const float* __restrict__ bo,
                             float* __restrict__ out) {
    int b = blockIdx.x, d = threadIdx.x;
    float s = 0.f;
    for (int c = 0; c < NCHUNK; c++) s += part[((size_t)b * NCHUNK + c) * DMODEL + d];
    out[b * DMODEL + d] = s * (1.0f / NTOK) * g[d] + bo[d];
}

// ---------------------------------------------------------------------------
// Launcher
// ---------------------------------------------------------------------------
extern "C" void kernel_launch(void* const* d_in, const int* in_sizes, int n_in,
                              void* d_out, int out_size) {
    const float* x       = (const float*)d_in[0];
    const float* patch_w = (const float*)d_in[1];
    const float* patch_b = (const float*)d_in[2];
    const float* pos     = (const float*)d_in[3];
    const float* imp_w1  = (const float*)d_in[4];
    const float* imp_b1  = (const float*)d_in[5];
    const float* imp_w2  = (const float*)d_in[6];
    const float* imp_b2  = (const float*)d_in[7];
    const float* ln1_g   = (const float*)d_in[8];
    const float* ln1_b   = (const float*)d_in[9];
    const float* qkv_w   = (const float*)d_in[10];
    const float* qkv_b   = (const float*)d_in[11];
    const float* proj_w  = (const float*)d_in[12];
    const float* proj_b  = (const float*)d_in[13];
    const float* ln2_g   = (const float*)d_in[14];
    const float* ln2_b   = (const float*)d_in[15];
    const float* mlp_w1  = (const float*)d_in[16];
    const float* mlp_b1  = (const float*)d_in[17];
    const float* mlp_w2  = (const float*)d_in[18];
    const float* mlp_b2  = (const float*)d_in[19];
    const float* out_g   = (const float*)d_in[20];
    const float* out_b   = (const float*)d_in[21];
    float* out = (float*)d_out;

    float *tokens, *hbuf, *scores, *part;
    __half *hln, *qkv, *attn, *mlp, *wt;
    float2* stats;
    int *mask, *idx;
    cudaGetSymbolAddress((void**)&tokens, g_tokens);
    cudaGetSymbolAddress((void**)&hbuf,   g_h);
    cudaGetSymbolAddress((void**)&hln,    g_hln);
    cudaGetSymbolAddress((void**)&qkv,    g_qkv);
    cudaGetSymbolAddress((void**)&attn,   g_attn);
    cudaGetSymbolAddress((void**)&mlp,    g_mlp);
    cudaGetSymbolAddress((void**)&scores, g_scores);
    cudaGetSymbolAddress((void**)&mask,   g_mask);
    cudaGetSymbolAddress((void**)&idx,    g_idx);
    cudaGetSymbolAddress((void**)&part,   g_part);
    cudaGetSymbolAddress((void**)&stats,  g_stats);
    cudaGetSymbolAddress((void**)&wt,     g_wt);

    cudaFuncSetAttribute((const void*)gemm_fp16<OUT_QKV, 3>,
                         cudaFuncAttributeMaxDynamicSharedMemorySize, GEMM_SMEM(3));
    cudaFuncSetAttribute((const void*)gemm_fp16<OUT_GELU, 4>,
                         cudaFuncAttributeMaxDynamicSharedMemorySize, GEMM_SMEM(4));
    cudaFuncSetAttribute((const void*)gemm_fp16<OUT_RES, 2>,
                         cudaFuncAttributeMaxDynamicSharedMemorySize, GEMM_SMEM(2));

    dim3 tb(32, 8);

    transpose_w<<<dim3(24, 8, 3), tb>>>(qkv_w, wt + OFF_QKV, DMODEL, 768);              // 0
    patch_kernel<<<MTOT, 256>>>(x, patch_w, patch_b, pos, tokens);                       // 1
    ln_half_kernel<<<MTOT / 8, 256>>>(tokens, ln1_g, ln1_b, hln);                        // 2
    gemm_fp16<OUT_QKV, 3><<<dim3(6, 96), 256, GEMM_SMEM(3)>>>(
        hln, wt + OFF_QKV, qkv_b, nullptr, nullptr, qkv, MTOT, 768, DMODEL);             // 3 (profiled)
    transpose_w<<<dim3(8, 8, 3), tb>>>(proj_w, wt + OFF_PROJ, DMODEL, DMODEL);           // 4
    transpose_w<<<dim3(32, 8, 3), tb>>>(mlp_w1, wt + OFF_MLP1, DMODEL, 1024);            // 5
    transpose_w<<<dim3(8, 32, 3), tb>>>(mlp_w2, wt + OFF_MLP2, 1024, DMODEL);            // 6
    gemm_f32_relu<<<dim3(DMODEL / 64, MTOT / 64), 256>>>(tokens, imp_w1, imp_b1,
                                                         hbuf, MTOT, DMODEL, DMODEL);    // 7
    score_kernel<<<MTOT / 8, 256>>>(hbuf, imp_w2, imp_b2, scores);                       // 8
    mask_kernel<<<MTOT / 8, 256>>>(scores, mask);                                        // 9
    compact_kernel<<<BATCH, 256>>>(mask, idx);                                           // 10

    for (int l = 0; l < DEPTH; l++) {
        if (l > 0) {
            ln_half_kernel<<<MTOT / 8, 256>>>(tokens, ln1_g + l * DMODEL,
                                              ln1_b + l * DMODEL, hln);
            gemm_fp16<OUT_QKV, 3><<<dim3(6, 96), 256, GEMM_SMEM(3)>>>(
                hln, wt + OFF_QKV + (size_t)l * DMODEL * 768, qkv_b + l * 768,
                nullptr, nullptr, qkv, MTOT, 768, DMODEL);
        }
        attn_fp16<<<dim3(NTOK / 256, NHEADS, BATCH), 256>>>(qkv, idx, attn);
        gemm_fp16<OUT_RES, 2><<<dim3(2, 144), 256, GEMM_SMEM(2)>>>(
            attn, wt + OFF_PROJ + (size_t)l * DMODEL * DMODEL, proj_b + l * DMODEL,
            tokens, tokens, nullptr, MTOT, DMODEL, DMODEL);
        ln_half_kernel<<<MTOT / 8, 256>>>(tokens, ln2_g + l * DMODEL,
                                          ln2_b + l * DMODEL, hln);
        gemm_fp16<OUT_GELU, 4><<<dim3(8, 72), 256, GEMM_SMEM(4)>>>(
            hln, wt + OFF_MLP1 + (size_t)l * DMODEL * 1024, mlp_b1 + l * 1024,
            nullptr, nullptr, mlp, MTOT, 1024, DMODEL);
        gemm_fp16<OUT_RES, 2><<<dim3(2, 144), 256, GEMM_SMEM(2)>>>(
            mlp, wt + OFF_MLP2 + (size_t)l * 1024 * DMODEL, mlp_b2 + l * DMODEL,
            tokens, tokens, nullptr, MTOT, DMODEL, 1024);
    }

    ln_stats_kernel<<<MTOT / 8, 256>>>(tokens, stats);
    mean1_kernel<<<dim3(NCHUNK, BATCH), 256>>>(tokens, stats, part);
    mean2_kernel<<<BATCH, 256>>>(part, out_g, out_b, out);
}

// round 16
// speedup vs baseline: 1.0865x; 1.0157x over previous
#include <cuda_runtime.h>
#include <cuda_fp16.h>
#include <math.h>

// ---------------------------------------------------------------------------
#define BATCH   4
#define NTOK    2304
#define DMODEL  256
#define NHEADS  8
#define DK      32
#define DEPTH   3
#define KDROP   345
#define NKEEP   (NTOK - KDROP)     // 1959
#define NPAD    1984               // 31 * 64
#define MTOT    (BATCH * NTOK)     // 9216
#define NCHUNK  36

// weight scratch offsets (halfs), transposed [N][K] layout
#define OFF_QKV  0
#define OFF_PROJ 589824
#define OFF_MLP1 786432
#define OFF_MLP2 1572864
#define WTOT     2359296

// GEMM 3-stage pipeline smem (bytes): stage = A(MT*32 x 40) + B(128 x 40) halfs
#define GEMM_SMEM(MT) (((MT) * 32 * 40 + 128 * 40) * 3 * 2)

// 1/sqrt(32) * log2(e), folded into Q at the QKV epilogue
#define SCALE2F 0.2550660030f

// ---------------------------------------------------------------------------
__device__ float  g_tokens[MTOT * DMODEL];
__device__ float  g_h     [MTOT * DMODEL];
__device__ __half g_hln   [MTOT * DMODEL];
__device__ __half g_qkv   [MTOT * 768];
__device__ __half g_attn  [MTOT * DMODEL];
__device__ __half g_mlp   [MTOT * 1024];   // MLP scratch; also A' for importance
__device__ float  g_scores[MTOT];
__device__ int    g_mask  [MTOT];
__device__ int    g_idx   [BATCH * NPAD];
__device__ float  g_part  [BATCH * NCHUNK * DMODEL];
__device__ float2 g_stats [MTOT];
__device__ __half g_wt    [WTOT];
__device__ __half g_wimp  [DMODEL * 768];  // split importance W1, [N][K'=768]

// ---------------------------------------------------------------------------
__device__ __forceinline__ unsigned packh2(float a, float b) {
    __half2 h = __floats2half2_rn(a, b);
    return *(unsigned*)&h;
}

__device__ __forceinline__ unsigned h2ex2(unsigned x) {
    unsigned r;
    asm("ex2.approx.f16x2 %0, %1;" : "=r"(r) : "r"(x));
    return r;
}

__device__ __forceinline__ void mma_f16(float c[4],
                                        unsigned a0, unsigned a1, unsigned a2, unsigned a3,
                                        unsigned b0, unsigned b1) {
    asm volatile(
        "mma.sync.aligned.m16n8k16.row.col.f32.f16.f16.f32 "
        "{%0,%1,%2,%3}, {%4,%5,%6,%7}, {%8,%9}, {%0,%1,%2,%3};"
        : "+f"(c[0]), "+f"(c[1]), "+f"(c[2]), "+f"(c[3])
        : "r"(a0), "r"(a1), "r"(a2), "r"(a3), "r"(b0), "r"(b1));
}

__device__ __forceinline__ void cpa16(void* smem, const void* g) {
    unsigned s = (unsigned)__cvta_generic_to_shared(smem);
    asm volatile("cp.async.ca.shared.global [%0], [%1], 16;" :: "r"(s), "l"(g));
}

__device__ __forceinline__ unsigned smaddr(const void* p) {
    return (unsigned)__cvta_generic_to_shared(p);
}

__device__ __forceinline__ void ldsm4(unsigned& r0, unsigned& r1, unsigned& r2, unsigned& r3,
                                      unsigned a) {
    asm volatile("ldmatrix.sync.aligned.m8n8.x4.shared.b16 {%0,%1,%2,%3}, [%4];"
                 : "=r"(r0), "=r"(r1), "=r"(r2), "=r"(r3) : "r"(a));
}

__device__ __forceinline__ void ldsm4t(unsigned& r0, unsigned& r1, unsigned& r2, unsigned& r3,
                                       unsigned a) {
    asm volatile("ldmatrix.sync.aligned.m8n8.x4.trans.shared.b16 {%0,%1,%2,%3}, [%4];"
                 : "=r"(r0), "=r"(r1), "=r"(r2), "=r"(r3) : "r"(a));
}

// ---------------------------------------------------------------------------
// Tiled transpose + f32->f16: W[L][K][N] -> WT[L][N][K] half
// ---------------------------------------------------------------------------
__global__ void transpose_w(const float* __restrict__ W, __half* __restrict__ WT,
                            int K, int N) {
    __shared__ float t[32][33];
    int n0 = blockIdx.x * 32, k0 = blockIdx.y * 32;
    int l = blockIdx.z;
    W  += (size_t)l * K * N;
    WT += (size_t)l * K * N;
    int tx = threadIdx.x, ty = threadIdx.y;
#pragma unroll
    for (int r = 0; r < 4; r++)
        t[ty + 8 * r][tx] = W[(size_t)(k0 + ty + 8 * r) * N + n0 + tx];
    __syncthreads();
#pragma unroll
    for (int r = 0; r < 4; r++)
        WT[(size_t)(n0 + ty + 8 * r) * K + k0 + tx] = __float2half(t[tx][ty + 8 * r]);
}

// ---------------------------------------------------------------------------
// Split importance W1 (f32 [K][N]) into WT' half [N][768]:
// cols [0:256)=hi, [256:512)=hi, [512:768)=lo  (pairs with A' = [Ah|Al|Ah])
// ---------------------------------------------------------------------------
__global__ void split_w_kernel(const float* __restrict__ W, __half* __restrict__ WTo) {
    int n = blockIdx.x, k = threadIdx.x;
    float w = W[(size_t)k * DMODEL + n];
    __half hi = __float2half(w);
    __half lo = __float2half(w - __half2float(hi));
    __half* o = WTo + (size_t)n * 768;
    o[k]       = hi;
    o[256 + k] = hi;
    o[512 + k] = lo;
}

// ---------------------------------------------------------------------------
// Split tokens (f32 [M][256]) into A' half [M][768]:
// cols [0:256)=hi, [256:512)=lo, [512:768)=hi
// ---------------------------------------------------------------------------
__global__ void split_a_kernel(const float* __restrict__ X, __half* __restrict__ Ao) {
    int t = blockIdx.x, d = threadIdx.x;
    float x = X[(size_t)t * DMODEL + d];
    __half hi = __float2half(x);
    __half lo = __float2half(x - __half2float(hi));
    __half* o = Ao + (size_t)t * 768;
    o[d]       = hi;
    o[256 + d] = lo;
    o[512 + d] = hi;
}

// ---------------------------------------------------------------------------
// Patch embed
// ---------------------------------------------------------------------------
__global__ void patch_kernel(const float* __restrict__ x,
                             const float* __restrict__ pw,
                             const float* __restrict__ pb,
                             const float* __restrict__ pos,
                             float* __restrict__ tokens) {
    int t = blockIdx.x;
    int b = t / NTOK, n = t % NTOK;
    int hc = n / 48, wc = n % 48;
    __shared__ float xs[12];
    if (threadIdx.x < 12) {
        int c = threadIdx.x / 4, pq = threadIdx.x % 4;
        int p = pq / 2, q = pq % 2;
        xs[threadIdx.x] = x[(((size_t)b * 3 + c) * 96 + (hc * 2 + p)) * 96 + (wc * 2 + q)];
    }
    __syncthreads();
    int d = threadIdx.x;
    float acc = pb[d];
#pragma unroll
    for (int e = 0; e < 12; e++) acc = fmaf(xs[e], pw[d * 12 + e], acc);
    tokens[(size_t)t * DMODEL + d] = acc + pos[(size_t)n * DMODEL + d];
}

// ---------------------------------------------------------------------------
// LayerNorm -> half output
// ---------------------------------------------------------------------------
__global__ void ln_half_kernel(const float* __restrict__ x,
                               const float* __restrict__ g,
                               const float* __restrict__ bta,
                               __half* __restrict__ y) {
    int t = blockIdx.x * 8 + (threadIdx.x >> 5);
    int lane = threadIdx.x & 31;
    const float* xp = x + (size_t)t * DMODEL + 8 * lane;
    float4 v0 = *(const float4*)xp;
    float4 v1 = *(const float4*)(xp + 4);
    float s = v0.x + v0.y + v0.z + v0.w + v1.x + v1.y + v1.z + v1.w;
#pragma unroll
    for (int o = 16; o > 0; o >>= 1) s += __shfl_xor_sync(0xffffffffu, s, o);
    float m = s * (1.0f / DMODEL);
    float vs = 0.f;
    float vv[8] = {v0.x, v0.y, v0.z, v0.w, v1.x, v1.y, v1.z, v1.w};
#pragma unroll
    for (int i = 0; i < 8; i++) { float d = vv[i] - m; vs = fmaf(d, d, vs); }
#pragma unroll
    for (int o = 16; o > 0; o >>= 1) vs += __shfl_xor_sync(0xffffffffu, vs, o);
    float rs = rsqrtf(vs * (1.0f / DMODEL) + 1e-5f);
    const float* gp = g + 8 * lane;
    const float* bp = bta + 8 * lane;
    __half2* yp = (__half2*)(y + (size_t)t * DMODEL + 8 * lane);
#pragma unroll
    for (int i = 0; i < 4; i++) {
        float g0 = gp[2 * i], g1 = gp[2 * i + 1];
        float b0 = bp[2 * i], b1 = bp[2 * i + 1];
        yp[i] = __floats2half2_rn((vv[2 * i] - m) * rs * g0 + b0,
                                  (vv[2 * i + 1] - m) * rs * g1 + b1);
    }
}

// ---------------------------------------------------------------------------
// LN stats (final LN only)
// ---------------------------------------------------------------------------
__global__ void ln_stats_kernel(const float* __restrict__ x, float2* __restrict__ st) {
    int t = blockIdx.x * 8 + (threadIdx.x >> 5);
    int lane = threadIdx.x & 31;
    const float* xp = x + (size_t)t * DMODEL;
    float v[8];
    float s = 0.f;
#pragma unroll
    for (int i = 0; i < 8; i++) { v[i] = xp[lane + 32 * i]; s += v[i]; }
#pragma unroll
    for (int o = 16; o > 0; o >>= 1) s += __shfl_xor_sync(0xffffffffu, s, o);
    float m = s * (1.0f / DMODEL);
    float vs = 0.f;
#pragma unroll
    for (int i = 0; i < 8; i++) { float d = v[i] - m; vs = fmaf(d, d, vs); }
#pragma unroll
    for (int o = 16; o > 0; o >>= 1) vs += __shfl_xor_sync(0xffffffffu, vs, o);
    float rs = rsqrtf(vs * (1.0f / DMODEL) + 1e-5f);
    if (lane == 0) { float2 o2 = {m, rs}; st[t] = o2; }
}

// ---------------------------------------------------------------------------
// FP16 tensor-core GEMM, 3-stage cp.async pipeline, ldmatrix fragments.
// Tile (MT*32)x128, BK=32, 256 threads. Warp tile (MT*16)x32.
// OUT_QKV: half out, Q cols (<256) pre-scaled. OUT_RELU: fp32 out + relu.
// ---------------------------------------------------------------------------
enum { OUT_HALF = 0, OUT_GELU = 1, OUT_RES = 2, OUT_QKV = 3, OUT_RELU = 4 };

template <int OUT, int MT>
__global__ __launch_bounds__(256, 2) void gemm_fp16(const __half* __restrict__ A,
                                                    const __half* __restrict__ WT,
                                                    const float* __restrict__ bias,
                                                    const float* res,
                                                    float* C,
                                                    __half* hout,
                                                    int M, int N, int K) {
    extern __shared__ __half dsm[];
    constexpr int ASTG = MT * 32 * 40;
    constexpr int BSTG = 128 * 40;
    constexpr int STG  = ASTG + BSTG;

    int m0 = blockIdx.y * (MT * 32), n0 = blockIdx.x * 128;
    int tid = threadIdx.x, warp = tid >> 5, lane = tid & 31;
    int tq = lane >> 2, tc = lane & 3;
    int mb = (warp >> 2) * (MT * 16), nb = (warp & 3) * 32;

    int aR = mb + (lane & 15);
    int aC = (lane >> 4) * 8;
    int bR = nb + ((lane >> 4) & 1) * 8 + (lane & 7);
    int bC = ((lane >> 3) & 1) * 8;

    auto issue = [&](int s, int it) {
        int k0 = it * 32;
#pragma unroll
        for (int c = tid; c < MT * 128; c += 256) {
            int row = c >> 2, seg = (c & 3) * 8;
            cpa16(dsm + s * STG + row * 40 + seg,
                  A + (size_t)(m0 + row) * K + k0 + seg);
        }
#pragma unroll
        for (int c = tid; c < 512; c += 256) {
            int row = c >> 2, seg = (c & 3) * 8;
            cpa16(dsm + s * STG + ASTG + row * 40 + seg,
                  WT + (size_t)(n0 + row) * K + k0 + seg);
        }
        asm volatile("cp.async.commit_group;");
    };

    float acc[MT][4][4] = {};
    int KT = K / 32;

    issue(0, 0);
    issue(1, 1);

    for (int it = 0; it < KT; ++it) {
        if (it < KT - 1) asm volatile("cp.async.wait_group 1;");
        else             asm volatile("cp.async.wait_group 0;");
        __syncthreads();
        if (it + 2 < KT) issue((it + 2) % 3, it + 2);

        const __half* A_s = dsm + (it % 3) * STG;
        const __half* B_s = A_s + ASTG;
#pragma unroll
        for (int ks = 0; ks < 2; ks++) {
            int kk = ks * 16;
            unsigned a[MT][4], b[4][2];
#pragma unroll
            for (int mt = 0; mt < MT; mt++)
                ldsm4(a[mt][0], a[mt][1], a[mt][2], a[mt][3],
                      smaddr(A_s + (aR + 16 * mt) * 40 + kk + aC));
#pragma unroll
            for (int p = 0; p < 2; p++)
                ldsm4(b[2 * p][0], b[2 * p][1], b[2 * p + 1][0], b[2 * p + 1][1],
                      smaddr(B_s + (bR + 16 * p) * 40 + kk + bC));
#pragma unroll
            for (int mt = 0; mt < MT; mt++)
#pragma unroll
                for (int nt = 0; nt < 4; nt++)
                    mma_f16(acc[mt][nt], a[mt][0], a[mt][1], a[mt][2], a[mt][3],
                            b[nt][0], b[nt][1]);
        }
    }

#pragma unroll
    for (int mt = 0; mt < MT; mt++) {
#pragma unroll
        for (int nt = 0; nt < 4; nt++) {
            int col = n0 + nb + 8 * nt + 2 * tc;
            float2 bb = *(const float2*)(bias + col);
#pragma unroll
            for (int hh = 0; hh < 2; hh++) {
                int row = m0 + mb + 16 * mt + tq + hh * 8;
                float u0 = acc[mt][nt][hh * 2 + 0] + bb.x;
                float u1 = acc[mt][nt][hh * 2 + 1] + bb.y;
                if (OUT == OUT_GELU) {
                    u0 = 0.5f * u0 * (1.0f + erff(u0 * 0.70710678118654752f));
                    u1 = 0.5f * u1 * (1.0f + erff(u1 * 0.70710678118654752f));
                }
                if (OUT == OUT_QKV && col < 256) {
                    u0 *= SCALE2F;
                    u1 *= SCALE2F;
                }
                if (OUT == OUT_RES) {
                    size_t base = (size_t)row * N + col;
                    float2 rr = *(const float2*)(res + base);
                    float2 ov = {u0 + rr.x, u1 + rr.y};
                    *(float2*)(C + base) = ov;
                } else if (OUT == OUT_RELU) {
                    size_t base = (size_t)row * N + col;
                    float2 ov = {fmaxf(u0, 0.f), fmaxf(u1, 0.f)};
                    *(float2*)(C + base) = ov;
                } else {
                    *(__half2*)(hout + (size_t)row * N + col) = __floats2half2_rn(u0, u1);
                }
            }
        }
    }
}

// ---------------------------------------------------------------------------
// Importance scores
// ---------------------------------------------------------------------------
__global__ void score_kernel(const float* __restrict__ h,
                             const float* __restrict__ w2,
                             const float* __restrict__ b2,
                             float* __restrict__ scores) {
    int t = blockIdx.x * 8 + (threadIdx.x >> 5);
    int lane = threadIdx.x & 31;
    const float* hp = h + (size_t)t * DMODEL;
    float s = 0.f;
#pragma unroll
    for (int i = 0; i < 8; i++) s = fmaf(hp[lane + 32 * i], w2[lane + 32 * i], s);
#pragma unroll
    for (int o = 16; o > 0; o >>= 1) s += __shfl_xor_sync(0xffffffffu, s, o);
    if (lane == 0) scores[t] = 1.0f / (1.0f + __expf(-(s + b2[0])));
}

// ---------------------------------------------------------------------------
// Bottom-k mask + compaction
// ---------------------------------------------------------------------------
__global__ void mask_kernel(const float* __restrict__ scores, int* __restrict__ mask) {
    int t = blockIdx.x * 8 + (threadIdx.x >> 5);
    int lane = threadIdx.x & 31;
    int b = t / NTOK, i = t % NTOK;
    const float* sb = scores + b * NTOK;
    float si = sb[i];
    int cnt = 0;
#pragma unroll 4
    for (int j = lane; j < NTOK; j += 32) {
        float sj = sb[j];
        cnt += (sj < si) || (sj == si && j < i);
    }
#pragma unroll
    for (int o = 16; o > 0; o >>= 1) cnt += __shfl_xor_sync(0xffffffffu, cnt, o);
    if (lane == 0) mask[t] = (cnt < KDROP) ? 1 : 0;
}

__global__ void compact_kernel(const int* __restrict__ mask, int* __restrict__ idx) {
    int b = blockIdx.x, tid = threadIdx.x;
    int lane = tid & 31, w = tid >> 5;
    const int* mb = mask + b * NTOK;
    int base = tid * 9;
    int keep[9], cnt = 0;
#pragma unroll
    for (int i = 0; i < 9; i++) {
        keep[i] = (mb[base + i] == 0);
        cnt += keep[i];
    }
    int inc = cnt;
#pragma unroll
    for (int o = 1; o < 32; o <<= 1) {
        int n = __shfl_up_sync(0xffffffffu, inc, o);
        if (lane >= o) inc += n;
    }
    __shared__ int wsum[8];
    if (lane == 31) wsum[w] = inc;
    __syncthreads();
    int woff = 0;
    for (int j = 0; j < w; j++) woff += wsum[j];
    int off = woff + inc - cnt;
    int* ob = idx + b * NPAD;
#pragma unroll
    for (int i = 0; i < 9; i++)
        if (keep[i]) ob[off++] = base + i;
    if (tid < NPAD - NKEEP) ob[NKEEP + tid] = 0;
}

// ---------------------------------------------------------------------------
// FP16 flash attention, 256-query tile, 3-stage async K/V ring.
// Max-free softmax, half2 exp2, ldmatrix frags, V via ldmatrix.trans.
// 256 threads: warp owns 32 q-rows (2 x 16-row groups).
// ---------------------------------------------------------------------------
__global__ __launch_bounds__(256, 2) void attn_fp16(const __half* __restrict__ qkv,
                                                    const int* __restrict__ idx,
                                                    __half* __restrict__ out) {
    __shared__ __half Ks[3][64][40];
    __shared__ __half Vs[3][64][40];
    __shared__ int    sidx[NPAD];

    int b = blockIdx.z, h = blockIdx.y;
    int q0 = blockIdx.x * 256;
    int tid = threadIdx.x;
    int w = tid >> 5, lane = tid & 31;
    int tq = lane >> 2, tc = lane & 3;
    int hoff = h * DK;

    int bR = ((lane >> 4) & 1) * 8 + (lane & 7);
    int bC = ((lane >> 3) & 1) * 8;
    int vR = lane & 15;
    int vC = (lane >> 4) * 8;

    const __half* qb = qkv + (size_t)b * NTOK * 768;

    for (int j = tid; j < NPAD; j += 256) sidx[j] = idx[b * NPAD + j];

    unsigned qa[2][2][4];
#pragma unroll
    for (int g = 0; g < 2; g++) {
        int rg = q0 + w * 32 + g * 16 + tq;
#pragma unroll
        for (int ks = 0; ks < 2; ks++) {
            int col = hoff + ks * 16 + 2 * tc;
            qa[g][ks][0] = *(const unsigned*)(qb + (size_t)rg * 768 + col);
            qa[g][ks][1] = *(const unsigned*)(qb + (size_t)(rg + 8) * 768 + col);
            qa[g][ks][2] = *(const unsigned*)(qb + (size_t)rg * 768 + col + 8);
            qa[g][ks][3] = *(const unsigned*)(qb + (size_t)(rg + 8) * 768 + col + 8);
        }
    }
    __syncthreads();   // sidx ready

    int krow = tid >> 2, kseg = tid & 3;
    auto issue = [&](int buf, int c0) {
        int t = sidx[c0 + krow];
        const __half* base = qb + (size_t)t * 768 + hoff + kseg * 8;
        cpa16(&Ks[buf][krow][kseg * 8], base + 256);
        cpa16(&Vs[buf][krow][kseg * 8], base + 512);
        asm volatile("cp.async.commit_group;");
    };

    const int NCH = NPAD / 64;
    issue(0, 0);
    issue(1, 64);

    float lsum[4] = {0.f, 0.f, 0.f, 0.f};
    float oacc[2][4][4] = {};

    for (int ci = 0; ci < NCH; ci++) {
        int buf = ci % 3;
        if (ci + 1 < NCH) asm volatile("cp.async.wait_group 1;");
        else              asm volatile("cp.async.wait_group 0;");
        __syncthreads();
        if (ci + 2 < NCH) issue((ci + 2) % 3, (ci + 2) * 64);

        unsigned pe[2][8], po[2][8];
#pragma unroll
        for (int g = 0; g < 2; g++) {
            float sacc[8][4] = {};
#pragma unroll
            for (int ks = 0; ks < 2; ks++) {
                int kk = ks * 16;
                unsigned kb[8][2];
#pragma unroll
                for (int p = 0; p < 4; p++)
                    ldsm4(kb[2 * p][0], kb[2 * p][1], kb[2 * p + 1][0], kb[2 * p + 1][1],
                          smaddr(&Ks[buf][bR + 16 * p][kk + bC]));
#pragma unroll
                for (int nt = 0; nt < 8; nt++)
                    mma_f16(sacc[nt], qa[g][ks][0], qa[g][ks][1], qa[g][ks][2],
                            qa[g][ks][3], kb[nt][0], kb[nt][1]);
            }

            if (ci == NCH - 1) {
                int c0 = ci * 64;
#pragma unroll
                for (int nt = 0; nt < 8; nt++) {
                    int jj = c0 + 8 * nt + 2 * tc;
                    if (jj >= NKEEP)     { sacc[nt][0] = -126.f; sacc[nt][2] = -126.f; }
                    if (jj + 1 >= NKEEP) { sacc[nt][1] = -126.f; sacc[nt][3] = -126.f; }
                }
            }

            __half2 lh0 = __float2half2_rn(0.f), lh1 = __float2half2_rn(0.f);
#pragma unroll
            for (int nt = 0; nt < 8; nt++) {
                pe[g][nt] = h2ex2(packh2(sacc[nt][0], sacc[nt][1]));
                po[g][nt] = h2ex2(packh2(sacc[nt][2], sacc[nt][3]));
                lh0 = __hadd2(lh0, *(__half2*)&pe[g][nt]);
                lh1 = __hadd2(lh1, *(__half2*)&po[g][nt]);
            }
            float2 lf0 = __half22float2(lh0);
            float2 lf1 = __half22float2(lh1);
            lsum[2 * g + 0] += lf0.x + lf0.y;
            lsum[2 * g + 1] += lf1.x + lf1.y;
        }

#pragma unroll
        for (int ks2 = 0; ks2 < 4; ks2++) {
            int kk = ks2 * 16;
            unsigned vb[4][2];
#pragma unroll
            for (int p = 0; p < 2; p++)
                ldsm4t(vb[2 * p][0], vb[2 * p][1], vb[2 * p + 1][0], vb[2 * p + 1][1],
                       smaddr(&Vs[buf][kk + vR][16 * p + vC]));
#pragma unroll
            for (int nt = 0; nt < 4; nt++) {
                mma_f16(oacc[0][nt], pe[0][2 * ks2], po[0][2 * ks2],
                        pe[0][2 * ks2 + 1], po[0][2 * ks2 + 1], vb[nt][0], vb[nt][1]);
                mma_f16(oacc[1][nt], pe[1][2 * ks2], po[1][2 * ks2],
                        pe[1][2 * ks2 + 1], po[1][2 * ks2 + 1], vb[nt][0], vb[nt][1]);
            }
        }
    }

#pragma unroll
    for (int i = 0; i < 4; i++) {
        lsum[i] += __shfl_xor_sync(0xffffffffu, lsum[i], 1);
        lsum[i] += __shfl_xor_sync(0xffffffffu, lsum[i], 2);
    }

#pragma unroll
    for (int g = 0; g < 2; g++) {
        float inv0 = 1.0f / lsum[2 * g + 0], inv1 = 1.0f / lsum[2 * g + 1];
        int r0 = b * NTOK + q0 + w * 32 + g * 16 + tq;
#pragma unroll
        for (int nt = 0; nt < 4; nt++) {
            int col = hoff + 8 * nt + 2 * tc;
            *(__half2*)(out + (size_t)r0 * DMODEL + col) =
                __floats2half2_rn(oacc[g][nt][0] * inv0, oacc[g][nt][1] * inv0);
            *(__half2*)(out + (size_t)(r0 + 8) * DMODEL + col) =
                __floats2half2_rn(oacc[g][nt][2] * inv1, oacc[g][nt][3] * inv1);
        }
    }
}

// ---------------------------------------------------------------------------
// Final LN + mean
// ---------------------------------------------------------------------------
__global__ void mean1_kernel(const float* __restrict__ x, const float2* __restrict__ st,
                             float* __restrict__ part) {
    int b = blockIdx.y, ch = blockIdx.x, d = threadIdx.x;
    const float* p = x + ((size_t)b * NTOK + ch * 64) * DMODEL + d;
    const float2* sp = st + b * NTOK + ch * 64;
    float s = 0.f;
#pragma unroll 8
    for (int n = 0; n < 64; n++) {
        float2 ms = sp[n];
        s += (p[(size_t)n * DMODEL] - ms.x) * ms.y;
    }
    part[((size_t)b * NCHUNK + ch) * DMODEL + d] = s;
}

__global__ void mean2_kernel(const float* __restrict__ part,
                             const float* __restrict__ g,
                             const float* __restrict__ bo,
                             float* __restrict__ out) {
    int b = blockIdx.x, d = threadIdx.x;
    float s = 0.f;
    for (int c = 0; c < NCHUNK; c++) s += part[((size_t)b * NCHUNK + c) * DMODEL + d];
    out[b * DMODEL + d] = s * (1.0f / NTOK) * g[d] + bo[d];
}

// ---------------------------------------------------------------------------
// Launcher
// ---------------------------------------------------------------------------
extern "C" void kernel_launch(void* const* d_in, const int* in_sizes, int n_in,
                              void* d_out, int out_size) {
    const float* x       = (const float*)d_in[0];
    const float* patch_w = (const float*)d_in[1];
    const float* patch_b = (const float*)d_in[2];
    const float* pos     = (const float*)d_in[3];
    const float* imp_w1  = (const float*)d_in[4];
    const float* imp_b1  = (const float*)d_in[5];
    const float* imp_w2  = (const float*)d_in[6];
    const float* imp_b2  = (const float*)d_in[7];
    const float* ln1_g   = (const float*)d_in[8];
    const float* ln1_b   = (const float*)d_in[9];
    const float* qkv_w   = (const float*)d_in[10];
    const float* qkv_b   = (const float*)d_in[11];
    const float* proj_w  = (const float*)d_in[12];
    const float* proj_b  = (const float*)d_in[13];
    const float* ln2_g   = (const float*)d_in[14];
    const float* ln2_b   = (const float*)d_in[15];
    const float* mlp_w1  = (const float*)d_in[16];
    const float* mlp_b1  = (const float*)d_in[17];
    const float* mlp_w2  = (const float*)d_in[18];
    const float* mlp_b2  = (const float*)d_in[19];
    const float* out_g   = (const float*)d_in[20];
    const float* out_b   = (const float*)d_in[21];
    float* out = (float*)d_out;

    float *tokens, *hbuf, *scores, *part;
    __half *hln, *qkv, *attn, *mlp, *wt, *wimp;
    float2* stats;
    int *mask, *idx;
    cudaGetSymbolAddress((void**)&tokens, g_tokens);
    cudaGetSymbolAddress((void**)&hbuf,   g_h);
    cudaGetSymbolAddress((void**)&hln,    g_hln);
    cudaGetSymbolAddress((void**)&qkv,    g_qkv);
    cudaGetSymbolAddress((void**)&attn,   g_attn);
    cudaGetSymbolAddress((void**)&mlp,    g_mlp);
    cudaGetSymbolAddress((void**)&scores, g_scores);
    cudaGetSymbolAddress((void**)&mask,   g_mask);
    cudaGetSymbolAddress((void**)&idx,    g_idx);
    cudaGetSymbolAddress((void**)&part,   g_part);
    cudaGetSymbolAddress((void**)&stats,  g_stats);
    cudaGetSymbolAddress((void**)&wt,     g_wt);
    cudaGetSymbolAddress((void**)&wimp,   g_wimp);

    cudaFuncSetAttribute((const void*)gemm_fp16<OUT_QKV, 3>,
                         cudaFuncAttributeMaxDynamicSharedMemorySize, GEMM_SMEM(3));
    cudaFuncSetAttribute((const void*)gemm_fp16<OUT_GELU, 4>,
                         cudaFuncAttributeMaxDynamicSharedMemorySize, GEMM_SMEM(4));
    cudaFuncSetAttribute((const void*)gemm_fp16<OUT_RES, 2>,
                         cudaFuncAttributeMaxDynamicSharedMemorySize, GEMM_SMEM(2));
    cudaFuncSetAttribute((const void*)gemm_fp16<OUT_RELU, 2>,
                         cudaFuncAttributeMaxDynamicSharedMemorySize, GEMM_SMEM(2));

    dim3 tb(32, 8);

    transpose_w<<<dim3(24, 8, 3), tb>>>(qkv_w, wt + OFF_QKV, DMODEL, 768);              // 0
    patch_kernel<<<MTOT, 256>>>(x, patch_w, patch_b, pos, tokens);                       // 1
    ln_half_kernel<<<MTOT / 8, 256>>>(tokens, ln1_g, ln1_b, hln);                        // 2
    gemm_fp16<OUT_QKV, 3><<<dim3(6, 96), 256, GEMM_SMEM(3)>>>(
        hln, wt + OFF_QKV, qkv_b, nullptr, nullptr, qkv, MTOT, 768, DMODEL);             // 3 (profiled)
    split_w_kernel<<<DMODEL, 256>>>(imp_w1, wimp);                                       // 4
    split_a_kernel<<<MTOT, 256>>>(tokens, mlp);                                          // 5
    gemm_fp16<OUT_RELU, 2><<<dim3(2, 144), 256, GEMM_SMEM(2)>>>(
        mlp, wimp, imp_b1, nullptr, hbuf, nullptr, MTOT, DMODEL, 768);                   // 6
    transpose_w<<<dim3(8, 8, 3), tb>>>(proj_w, wt + OFF_PROJ, DMODEL, DMODEL);           // 7
    transpose_w<<<dim3(32, 8, 3), tb>>>(mlp_w1, wt + OFF_MLP1, DMODEL, 1024);            // 8
    transpose_w<<<dim3(8, 32, 3), tb>>>(mlp_w2, wt + OFF_MLP2, 1024, DMODEL);            // 9
    score_kernel<<<MTOT / 8, 256>>>(hbuf, imp_w2, imp_b2, scores);                       // 10
    mask_kernel<<<MTOT / 8, 256>>>(scores, mask);                                        // 11
    compact_kernel<<<BATCH, 256>>>(mask, idx);                                           // 12

    for (int l = 0; l < DEPTH; l++) {
        if (l > 0) {
            ln_half_kernel<<<MTOT / 8, 256>>>(tokens, ln1_g + l * DMODEL,
                                              ln1_b + l * DMODEL, hln);
            gemm_fp16<OUT_QKV, 3><<<dim3(6, 96), 256, GEMM_SMEM(3)>>>(
                hln, wt + OFF_QKV + (size_t)l * DMODEL * 768, qkv_b + l * 768,
                nullptr, nullptr, qkv, MTOT, 768, DMODEL);
        }
        attn_fp16<<<dim3(NTOK / 256, NHEADS, BATCH), 256>>>(qkv, idx, attn);
        gemm_fp16<OUT_RES, 2><<<dim3(2, 144), 256, GEMM_SMEM(2)>>>(
            attn, wt + OFF_PROJ + (size_t)l * DMODEL * DMODEL, proj_b + l * DMODEL,
            tokens, tokens, nullptr, MTOT, DMODEL, DMODEL);
        ln_half_kernel<<<MTOT / 8, 256>>>(tokens, ln2_g + l * DMODEL,
                                          ln2_b + l * DMODEL, hln);
        gemm_fp16<OUT_GELU, 4><<<dim3(8, 72), 256, GEMM_SMEM(4)>>>(
            hln, wt + OFF_MLP1 + (size_t)l * DMODEL * 1024, mlp_b1 + l * 1024,
            nullptr, nullptr, mlp, MTOT, 1024, DMODEL);
        gemm_fp16<OUT_RES, 2><<<dim3(2, 144), 256, GEMM_SMEM(2)>>>(
            mlp, wt + OFF_MLP2 + (size_t)l * 1024 * DMODEL, mlp_b2 + l * DMODEL,
            tokens, tokens, nullptr, MTOT, DMODEL, 1024);
    }

    ln_stats_kernel<<<MTOT / 8, 256>>>(tokens, stats);
    mean1_kernel<<<dim3(NCHUNK, BATCH), 256>>>(tokens, stats, part);
    mean2_kernel<<<BATCH, 256>>>(part, out_g, out_b, out);
}

// round 17
// speedup vs baseline: 1.1111x; 1.0226x over previous
#include <cuda_runtime.h>
#include <cuda_fp16.h>
#include <math.h>

// ---------------------------------------------------------------------------
#define BATCH   4
#define NTOK    2304
#define DMODEL  256
#define NHEADS  8
#define DK      32
#define DEPTH   3
#define KDROP   345
#define NKEEP   (NTOK - KDROP)     // 1959
#define NPAD    1984               // 31 * 64
#define MTOT    (BATCH * NTOK)     // 9216
#define NCHUNK  36

// weight scratch offsets (halfs), transposed [N][K] layout
#define OFF_QKV  0
#define OFF_PROJ 589824
#define OFF_MLP1 786432
#define OFF_MLP2 1572864
#define WTOT     2359296

// GEMM 3-stage pipeline smem (bytes): stage = A(MT*32 x 40) + B(128 x 40) halfs
#define GEMM_SMEM(MT) (((MT) * 32 * 40 + 128 * 40) * 3 * 2)

// 1/sqrt(32) * log2(e), folded into Q at the QKV epilogue
#define SCALE2F 0.2550660030f

// ---------------------------------------------------------------------------
__device__ float  g_tokens[MTOT * DMODEL];
__device__ float  g_h     [MTOT * DMODEL];
__device__ __half g_hln   [MTOT * DMODEL];
__device__ __half g_qkv   [MTOT * 768];
__device__ __half g_attn  [MTOT * DMODEL];
__device__ __half g_mlp   [MTOT * 1024];   // MLP scratch; also A' for importance
__device__ float  g_scores[MTOT];
__device__ int    g_mask  [MTOT];
__device__ int    g_idx   [BATCH * NPAD];
__device__ float  g_part  [BATCH * NCHUNK * DMODEL];
__device__ __half g_wt    [WTOT];
__device__ __half g_wimp  [DMODEL * 768];  // split importance W1, [N][K'=768]

// ---------------------------------------------------------------------------
__device__ __forceinline__ unsigned packh2(float a, float b) {
    __half2 h = __floats2half2_rn(a, b);
    return *(unsigned*)&h;
}

__device__ __forceinline__ unsigned h2ex2(unsigned x) {
    unsigned r;
    asm("ex2.approx.f16x2 %0, %1;" : "=r"(r) : "r"(x));
    return r;
}

__device__ __forceinline__ void mma_f16(float c[4],
                                        unsigned a0, unsigned a1, unsigned a2, unsigned a3,
                                        unsigned b0, unsigned b1) {
    asm volatile(
        "mma.sync.aligned.m16n8k16.row.col.f32.f16.f16.f32 "
        "{%0,%1,%2,%3}, {%4,%5,%6,%7}, {%8,%9}, {%0,%1,%2,%3};"
        : "+f"(c[0]), "+f"(c[1]), "+f"(c[2]), "+f"(c[3])
        : "r"(a0), "r"(a1), "r"(a2), "r"(a3), "r"(b0), "r"(b1));
}

__device__ __forceinline__ void cpa16(void* smem, const void* g) {
    unsigned s = (unsigned)__cvta_generic_to_shared(smem);
    asm volatile("cp.async.ca.shared.global [%0], [%1], 16;" :: "r"(s), "l"(g));
}

__device__ __forceinline__ unsigned smaddr(const void* p) {
    return (unsigned)__cvta_generic_to_shared(p);
}

__device__ __forceinline__ void ldsm4(unsigned& r0, unsigned& r1, unsigned& r2, unsigned& r3,
                                      unsigned a) {
    asm volatile("ldmatrix.sync.aligned.m8n8.x4.shared.b16 {%0,%1,%2,%3}, [%4];"
                 : "=r"(r0), "=r"(r1), "=r"(r2), "=r"(r3) : "r"(a));
}

__device__ __forceinline__ void ldsm4t(unsigned& r0, unsigned& r1, unsigned& r2, unsigned& r3,
                                       unsigned a) {
    asm volatile("ldmatrix.sync.aligned.m8n8.x4.trans.shared.b16 {%0,%1,%2,%3}, [%4];"
                 : "=r"(r0), "=r"(r1), "=r"(r2), "=r"(r3) : "r"(a));
}

// ---------------------------------------------------------------------------
// Tiled transpose + f32->f16: W[L][K][N] -> WT[L][N][K] half
// ---------------------------------------------------------------------------
__global__ void transpose_w(const float* __restrict__ W, __half* __restrict__ WT,
                            int K, int N) {
    __shared__ float t[32][33];
    int n0 = blockIdx.x * 32, k0 = blockIdx.y * 32;
    int l = blockIdx.z;
    W  += (size_t)l * K * N;
    WT += (size_t)l * K * N;
    int tx = threadIdx.x, ty = threadIdx.y;
#pragma unroll
    for (int r = 0; r < 4; r++)
        t[ty + 8 * r][tx] = W[(size_t)(k0 + ty + 8 * r) * N + n0 + tx];
    __syncthreads();
#pragma unroll
    for (int r = 0; r < 4; r++)
        WT[(size_t)(n0 + ty + 8 * r) * K + k0 + tx] = __float2half(t[tx][ty + 8 * r]);
}

// ---------------------------------------------------------------------------
// Split importance W1 (f32 [K][N]) into WT' half [N][768]:
// cols [0:256)=hi, [256:512)=hi, [512:768)=lo  (pairs with A' = [Ah|Al|Ah])
// ---------------------------------------------------------------------------
__global__ void split_w_kernel(const float* __restrict__ W, __half* __restrict__ WTo) {
    int n = blockIdx.x, k = threadIdx.x;
    float w = W[(size_t)k * DMODEL + n];
    __half hi = __float2half(w);
    __half lo = __float2half(w - __half2float(hi));
    __half* o = WTo + (size_t)n * 768;
    o[k]       = hi;
    o[256 + k] = hi;
    o[512 + k] = lo;
}

// ---------------------------------------------------------------------------
// FUSED patch embed + layer-0 LN (-> hln) + hi/lo split (-> A' for importance).
// Block = one token, 256 threads = 256 dims. Exact two-pass LN.
// ---------------------------------------------------------------------------
__global__ void patch_fused_kernel(const float* __restrict__ x,
                                   const float* __restrict__ pw,
                                   const float* __restrict__ pb,
                                   const float* __restrict__ pos,
                                   const float* __restrict__ lg,
                                   const float* __restrict__ lb,
                                   float* __restrict__ tokens,
                                   __half* __restrict__ hln,
                                   __half* __restrict__ asplit) {
    int t = blockIdx.x;
    int b = t / NTOK, n = t % NTOK;
    int hc = n / 48, wc = n % 48;
    __shared__ float xs[12];
    __shared__ float red[8];
    int tid = threadIdx.x, w = tid >> 5, lane = tid & 31;
    if (tid < 12) {
        int c = tid / 4, pq = tid % 4;
        int p = pq / 2, q = pq % 2;
        xs[tid] = x[(((size_t)b * 3 + c) * 96 + (hc * 2 + p)) * 96 + (wc * 2 + q)];
    }
    __syncthreads();
    int d = tid;
    float acc = pb[d];
#pragma unroll
    for (int e = 0; e < 12; e++) acc = fmaf(xs[e], pw[d * 12 + e], acc);
    acc += pos[(size_t)n * DMODEL + d];
    tokens[(size_t)t * DMODEL + d] = acc;

    // pass 1: mean
    float s = acc;
#pragma unroll
    for (int o = 16; o > 0; o >>= 1) s += __shfl_xor_sync(0xffffffffu, s, o);
    if (lane == 0) red[w] = s;
    __syncthreads();
    s = red[0] + red[1] + red[2] + red[3] + red[4] + red[5] + red[6] + red[7];
    float m = s * (1.0f / DMODEL);
    __syncthreads();
    // pass 2: variance
    float dv = acc - m;
    float q = dv * dv;
#pragma unroll
    for (int o = 16; o > 0; o >>= 1) q += __shfl_xor_sync(0xffffffffu, q, o);
    if (lane == 0) red[w] = q;
    __syncthreads();
    q = red[0] + red[1] + red[2] + red[3] + red[4] + red[5] + red[6] + red[7];
    float rs = rsqrtf(q * (1.0f / DMODEL) + 1e-5f);

    hln[(size_t)t * DMODEL + d] = __float2half(dv * rs * lg[d] + lb[d]);

    __half hi = __float2half(acc);
    __half lo = __float2half(acc - __half2float(hi));
    __half* o = asplit + (size_t)t * 768;
    o[d]       = hi;
    o[256 + d] = lo;
    o[512 + d] = hi;
}

// ---------------------------------------------------------------------------
// LayerNorm -> half output (mid-network layers)
// ---------------------------------------------------------------------------
__global__ void ln_half_kernel(const float* __restrict__ x,
                               const float* __restrict__ g,
                               const float* __restrict__ bta,
                               __half* __restrict__ y) {
    int t = blockIdx.x * 8 + (threadIdx.x >> 5);
    int lane = threadIdx.x & 31;
    const float* xp = x + (size_t)t * DMODEL + 8 * lane;
    float4 v0 = *(const float4*)xp;
    float4 v1 = *(const float4*)(xp + 4);
    float s = v0.x + v0.y + v0.z + v0.w + v1.x + v1.y + v1.z + v1.w;
#pragma unroll
    for (int o = 16; o > 0; o >>= 1) s += __shfl_xor_sync(0xffffffffu, s, o);
    float m = s * (1.0f / DMODEL);
    float vs = 0.f;
    float vv[8] = {v0.x, v0.y, v0.z, v0.w, v1.x, v1.y, v1.z, v1.w};
#pragma unroll
    for (int i = 0; i < 8; i++) { float d = vv[i] - m; vs = fmaf(d, d, vs); }
#pragma unroll
    for (int o = 16; o > 0; o >>= 1) vs += __shfl_xor_sync(0xffffffffu, vs, o);
    float rs = rsqrtf(vs * (1.0f / DMODEL) + 1e-5f);
    const float* gp = g + 8 * lane;
    const float* bp = bta + 8 * lane;
    __half2* yp = (__half2*)(y + (size_t)t * DMODEL + 8 * lane);
#pragma unroll
    for (int i = 0; i < 4; i++) {
        float g0 = gp[2 * i], g1 = gp[2 * i + 1];
        float b0 = bp[2 * i], b1 = bp[2 * i + 1];
        yp[i] = __floats2half2_rn((vv[2 * i] - m) * rs * g0 + b0,
                                  (vv[2 * i + 1] - m) * rs * g1 + b1);
    }
}

// ---------------------------------------------------------------------------
// FP16 tensor-core GEMM, 3-stage cp.async pipeline, ldmatrix fragments.
// Tile (MT*32)x128, BK=32, 256 threads. Warp tile (MT*16)x32.
// ---------------------------------------------------------------------------
enum { OUT_HALF = 0, OUT_GELU = 1, OUT_RES = 2, OUT_QKV = 3, OUT_RELU = 4 };

template <int OUT, int MT>
__global__ __launch_bounds__(256, 2) void gemm_fp16(const __half* __restrict__ A,
                                                    const __half* __restrict__ WT,
                                                    const float* __restrict__ bias,
                                                    const float* res,
                                                    float* C,
                                                    __half* hout,
                                                    int M, int N, int K) {
    extern __shared__ __half dsm[];
    constexpr int ASTG = MT * 32 * 40;
    constexpr int BSTG = 128 * 40;
    constexpr int STG  = ASTG + BSTG;

    int m0 = blockIdx.y * (MT * 32), n0 = blockIdx.x * 128;
    int tid = threadIdx.x, warp = tid >> 5, lane = tid & 31;
    int tq = lane >> 2, tc = lane & 3;
    int mb = (warp >> 2) * (MT * 16), nb = (warp & 3) * 32;

    int aR = mb + (lane & 15);
    int aC = (lane >> 4) * 8;
    int bR = nb + ((lane >> 4) & 1) * 8 + (lane & 7);
    int bC = ((lane >> 3) & 1) * 8;

    auto issue = [&](int s, int it) {
        int k0 = it * 32;
#pragma unroll
        for (int c = tid; c < MT * 128; c += 256) {
            int row = c >> 2, seg = (c & 3) * 8;
            cpa16(dsm + s * STG + row * 40 + seg,
                  A + (size_t)(m0 + row) * K + k0 + seg);
        }
#pragma unroll
        for (int c = tid; c < 512; c += 256) {
            int row = c >> 2, seg = (c & 3) * 8;
            cpa16(dsm + s * STG + ASTG + row * 40 + seg,
                  WT + (size_t)(n0 + row) * K + k0 + seg);
        }
        asm volatile("cp.async.commit_group;");
    };

    float acc[MT][4][4] = {};
    int KT = K / 32;

    issue(0, 0);
    issue(1, 1);

    for (int it = 0; it < KT; ++it) {
        if (it < KT - 1) asm volatile("cp.async.wait_group 1;");
        else             asm volatile("cp.async.wait_group 0;");
        __syncthreads();
        if (it + 2 < KT) issue((it + 2) % 3, it + 2);

        const __half* A_s = dsm + (it % 3) * STG;
        const __half* B_s = A_s + ASTG;
#pragma unroll
        for (int ks = 0; ks < 2; ks++) {
            int kk = ks * 16;
            unsigned a[MT][4], b[4][2];
#pragma unroll
            for (int mt = 0; mt < MT; mt++)
                ldsm4(a[mt][0], a[mt][1], a[mt][2], a[mt][3],
                      smaddr(A_s + (aR + 16 * mt) * 40 + kk + aC));
#pragma unroll
            for (int p = 0; p < 2; p++)
                ldsm4(b[2 * p][0], b[2 * p][1], b[2 * p + 1][0], b[2 * p + 1][1],
                      smaddr(B_s + (bR + 16 * p) * 40 + kk + bC));
#pragma unroll
            for (int mt = 0; mt < MT; mt++)
#pragma unroll
                for (int nt = 0; nt < 4; nt++)
                    mma_f16(acc[mt][nt], a[mt][0], a[mt][1], a[mt][2], a[mt][3],
                            b[nt][0], b[nt][1]);
        }
    }

#pragma unroll
    for (int mt = 0; mt < MT; mt++) {
#pragma unroll
        for (int nt = 0; nt < 4; nt++) {
            int col = n0 + nb + 8 * nt + 2 * tc;
            float2 bb = *(const float2*)(bias + col);
#pragma unroll
            for (int hh = 0; hh < 2; hh++) {
                int row = m0 + mb + 16 * mt + tq + hh * 8;
                float u0 = acc[mt][nt][hh * 2 + 0] + bb.x;
                float u1 = acc[mt][nt][hh * 2 + 1] + bb.y;
                if (OUT == OUT_GELU) {
                    u0 = 0.5f * u0 * (1.0f + erff(u0 * 0.70710678118654752f));
                    u1 = 0.5f * u1 * (1.0f + erff(u1 * 0.70710678118654752f));
                }
                if (OUT == OUT_QKV && col < 256) {
                    u0 *= SCALE2F;
                    u1 *= SCALE2F;
                }
                if (OUT == OUT_RES) {
                    size_t base = (size_t)row * N + col;
                    float2 rr = *(const float2*)(res + base);
                    float2 ov = {u0 + rr.x, u1 + rr.y};
                    *(float2*)(C + base) = ov;
                } else if (OUT == OUT_RELU) {
                    size_t base = (size_t)row * N + col;
                    float2 ov = {fmaxf(u0, 0.f), fmaxf(u1, 0.f)};
                    *(float2*)(C + base) = ov;
                } else {
                    *(__half2*)(hout + (size_t)row * N + col) = __floats2half2_rn(u0, u1);
                }
            }
        }
    }
}

// ---------------------------------------------------------------------------
// Importance scores
// ---------------------------------------------------------------------------
__global__ void score_kernel(const float* __restrict__ h,
                             const float* __restrict__ w2,
                             const float* __restrict__ b2,
                             float* __restrict__ scores) {
    int t = blockIdx.x * 8 + (threadIdx.x >> 5);
    int lane = threadIdx.x & 31;
    const float* hp = h + (size_t)t * DMODEL;
    float s = 0.f;
#pragma unroll
    for (int i = 0; i < 8; i++) s = fmaf(hp[lane + 32 * i], w2[lane + 32 * i], s);
#pragma unroll
    for (int o = 16; o > 0; o >>= 1) s += __shfl_xor_sync(0xffffffffu, s, o);
    if (lane == 0) scores[t] = 1.0f / (1.0f + __expf(-(s + b2[0])));
}

// ---------------------------------------------------------------------------
// Bottom-k mask + compaction
// ---------------------------------------------------------------------------
__global__ void mask_kernel(const float* __restrict__ scores, int* __restrict__ mask) {
    int t = blockIdx.x * 8 + (threadIdx.x >> 5);
    int lane = threadIdx.x & 31;
    int b = t / NTOK, i = t % NTOK;
    const float* sb = scores + b * NTOK;
    float si = sb[i];
    int cnt = 0;
#pragma unroll 4
    for (int j = lane; j < NTOK; j += 32) {
        float sj = sb[j];
        cnt += (sj < si) || (sj == si && j < i);
    }
#pragma unroll
    for (int o = 16; o > 0; o >>= 1) cnt += __shfl_xor_sync(0xffffffffu, cnt, o);
    if (lane == 0) mask[t] = (cnt < KDROP) ? 1 : 0;
}

__global__ void compact_kernel(const int* __restrict__ mask, int* __restrict__ idx) {
    int b = blockIdx.x, tid = threadIdx.x;
    int lane = tid & 31, w = tid >> 5;
    const int* mb = mask + b * NTOK;
    int base = tid * 9;
    int keep[9], cnt = 0;
#pragma unroll
    for (int i = 0; i < 9; i++) {
        keep[i] = (mb[base + i] == 0);
        cnt += keep[i];
    }
    int inc = cnt;
#pragma unroll
    for (int o = 1; o < 32; o <<= 1) {
        int n = __shfl_up_sync(0xffffffffu, inc, o);
        if (lane >= o) inc += n;
    }
    __shared__ int wsum[8];
    if (lane == 31) wsum[w] = inc;
    __syncthreads();
    int woff = 0;
    for (int j = 0; j < w; j++) woff += wsum[j];
    int off = woff + inc - cnt;
    int* ob = idx + b * NPAD;
#pragma unroll
    for (int i = 0; i < 9; i++)
        if (keep[i]) ob[off++] = base + i;
    if (tid < NPAD - NKEEP) ob[NKEEP + tid] = 0;
}

// ---------------------------------------------------------------------------
// FP16 flash attention, 256-query tile, 3-stage async K/V ring.
// Max-free softmax, half2 exp2, ldmatrix frags, V via ldmatrix.trans.
// 256 threads: warp owns 32 q-rows (2 x 16-row groups).
// ---------------------------------------------------------------------------
__global__ __launch_bounds__(256, 2) void attn_fp16(const __half* __restrict__ qkv,
                                                    const int* __restrict__ idx,
                                                    __half* __restrict__ out) {
    __shared__ __half Ks[3][64][40];
    __shared__ __half Vs[3][64][40];
    __shared__ int    sidx[NPAD];

    int b = blockIdx.z, h = blockIdx.y;
    int q0 = blockIdx.x * 256;
    int tid = threadIdx.x;
    int w = tid >> 5, lane = tid & 31;
    int tq = lane >> 2, tc = lane & 3;
    int hoff = h * DK;

    int bR = ((lane >> 4) & 1) * 8 + (lane & 7);
    int bC = ((lane >> 3) & 1) * 8;
    int vR = lane & 15;
    int vC = (lane >> 4) * 8;

    const __half* qb = qkv + (size_t)b * NTOK * 768;

    for (int j = tid; j < NPAD; j += 256) sidx[j] = idx[b * NPAD + j];

    unsigned qa[2][2][4];
#pragma unroll
    for (int g = 0; g < 2; g++) {
        int rg = q0 + w * 32 + g * 16 + tq;
#pragma unroll
        for (int ks = 0; ks < 2; ks++) {
            int col = hoff + ks * 16 + 2 * tc;
            qa[g][ks][0] = *(const unsigned*)(qb + (size_t)rg * 768 + col);
            qa[g][ks][1] = *(const unsigned*)(qb + (size_t)(rg + 8) * 768 + col);
            qa[g][ks][2] = *(const unsigned*)(qb + (size_t)rg * 768 + col + 8);
            qa[g][ks][3] = *(const unsigned*)(qb + (size_t)(rg + 8) * 768 + col + 8);
        }
    }
    __syncthreads();   // sidx ready

    int krow = tid >> 2, kseg = tid & 3;
    auto issue = [&](int buf, int c0) {
        int t = sidx[c0 + krow];
        const __half* base = qb + (size_t)t * 768 + hoff + kseg * 8;
        cpa16(&Ks[buf][krow][kseg * 8], base + 256);
        cpa16(&Vs[buf][krow][kseg * 8], base + 512);
        asm volatile("cp.async.commit_group;");
    };

    const int NCH = NPAD / 64;
    issue(0, 0);
    issue(1, 64);

    float lsum[4] = {0.f, 0.f, 0.f, 0.f};
    float oacc[2][4][4] = {};

    for (int ci = 0; ci < NCH; ci++) {
        int buf = ci % 3;
        if (ci + 1 < NCH) asm volatile("cp.async.wait_group 1;");
        else              asm volatile("cp.async.wait_group 0;");
        __syncthreads();
        if (ci + 2 < NCH) issue((ci + 2) % 3, (ci + 2) * 64);

        unsigned pe[2][8], po[2][8];
#pragma unroll
        for (int g = 0; g < 2; g++) {
            float sacc[8][4] = {};
#pragma unroll
            for (int ks = 0; ks < 2; ks++) {
                int kk = ks * 16;
                unsigned kb[8][2];
#pragma unroll
                for (int p = 0; p < 4; p++)
                    ldsm4(kb[2 * p][0], kb[2 * p][1], kb[2 * p + 1][0], kb[2 * p + 1][1],
                          smaddr(&Ks[buf][bR + 16 * p][kk + bC]));
#pragma unroll
                for (int nt = 0; nt < 8; nt++)
                    mma_f16(sacc[nt], qa[g][ks][0], qa[g][ks][1], qa[g][ks][2],
                            qa[g][ks][3], kb[nt][0], kb[nt][1]);
            }

            if (ci == NCH - 1) {
                int c0 = ci * 64;
#pragma unroll
                for (int nt = 0; nt < 8; nt++) {
                    int jj = c0 + 8 * nt + 2 * tc;
                    if (jj >= NKEEP)     { sacc[nt][0] = -126.f; sacc[nt][2] = -126.f; }
                    if (jj + 1 >= NKEEP) { sacc[nt][1] = -126.f; sacc[nt][3] = -126.f; }
                }
            }

            __half2 lh0 = __float2half2_rn(0.f), lh1 = __float2half2_rn(0.f);
#pragma unroll
            for (int nt = 0; nt < 8; nt++) {
                pe[g][nt] = h2ex2(packh2(sacc[nt][0], sacc[nt][1]));
                po[g][nt] = h2ex2(packh2(sacc[nt][2], sacc[nt][3]));
                lh0 = __hadd2(lh0, *(__half2*)&pe[g][nt]);
                lh1 = __hadd2(lh1, *(__half2*)&po[g][nt]);
            }
            float2 lf0 = __half22float2(lh0);
            float2 lf1 = __half22float2(lh1);
            lsum[2 * g + 0] += lf0.x + lf0.y;
            lsum[2 * g + 1] += lf1.x + lf1.y;
        }

#pragma unroll
        for (int ks2 = 0; ks2 < 4; ks2++) {
            int kk = ks2 * 16;
            unsigned vb[4][2];
#pragma unroll
            for (int p = 0; p < 2; p++)
                ldsm4t(vb[2 * p][0], vb[2 * p][1], vb[2 * p + 1][0], vb[2 * p + 1][1],
                       smaddr(&Vs[buf][kk + vR][16 * p + vC]));
#pragma unroll
            for (int nt = 0; nt < 4; nt++) {
                mma_f16(oacc[0][nt], pe[0][2 * ks2], po[0][2 * ks2],
                        pe[0][2 * ks2 + 1], po[0][2 * ks2 + 1], vb[nt][0], vb[nt][1]);
                mma_f16(oacc[1][nt], pe[1][2 * ks2], po[1][2 * ks2],
                        pe[1][2 * ks2 + 1], po[1][2 * ks2 + 1], vb[nt][0], vb[nt][1]);
            }
        }
    }

#pragma unroll
    for (int i = 0; i < 4; i++) {
        lsum[i] += __shfl_xor_sync(0xffffffffu, lsum[i], 1);
        lsum[i] += __shfl_xor_sync(0xffffffffu, lsum[i], 2);
    }

#pragma unroll
    for (int g = 0; g < 2; g++) {
        float inv0 = 1.0f / lsum[2 * g + 0], inv1 = 1.0f / lsum[2 * g + 1];
        int r0 = b * NTOK + q0 + w * 32 + g * 16 + tq;
#pragma unroll
        for (int nt = 0; nt < 4; nt++) {
            int col = hoff + 8 * nt + 2 * tc;
            *(__half2*)(out + (size_t)r0 * DMODEL + col) =
                __floats2half2_rn(oacc[g][nt][0] * inv0, oacc[g][nt][1] * inv0);
            *(__half2*)(out + (size_t)(r0 + 8) * DMODEL + col) =
                __floats2half2_rn(oacc[g][nt][2] * inv1, oacc[g][nt][3] * inv1);
        }
    }
}

// ---------------------------------------------------------------------------
// FUSED final LN stats + partial mean. Block = 64 tokens; warp handles 8
// tokens sequentially (lane owns dims 8*lane..8*lane+7); smem reduce.
// ---------------------------------------------------------------------------
__global__ void mean1_fused(const float* __restrict__ x, float* __restrict__ part) {
    __shared__ float pacc[8][DMODEL];
    int b = blockIdx.y, ch = blockIdx.x;
    int tid = threadIdx.x, w = tid >> 5, lane = tid & 31;

    const float* base = x + ((size_t)b * NTOK + ch * 64 + w * 8) * DMODEL + 8 * lane;
    float a[8] = {};
#pragma unroll
    for (int i = 0; i < 8; i++) {
        float4 v0 = *(const float4*)(base + (size_t)i * DMODEL);
        float4 v1 = *(const float4*)(base + (size_t)i * DMODEL + 4);
        float vv[8] = {v0.x, v0.y, v0.z, v0.w, v1.x, v1.y, v1.z, v1.w};
        float s = vv[0] + vv[1] + vv[2] + vv[3] + vv[4] + vv[5] + vv[6] + vv[7];
#pragma unroll
        for (int o = 16; o > 0; o >>= 1) s += __shfl_xor_sync(0xffffffffu, s, o);
        float m = s * (1.0f / DMODEL);
        float vs = 0.f;
#pragma unroll
        for (int j = 0; j < 8; j++) { float d = vv[j] - m; vs = fmaf(d, d, vs); }
#pragma unroll
        for (int o = 16; o > 0; o >>= 1) vs += __shfl_xor_sync(0xffffffffu, vs, o);
        float rs = rsqrtf(vs * (1.0f / DMODEL) + 1e-5f);
#pragma unroll
        for (int j = 0; j < 8; j++) a[j] += (vv[j] - m) * rs;
    }
#pragma unroll
    for (int j = 0; j < 8; j++) pacc[w][8 * lane + j] = a[j];
    __syncthreads();
    int d = tid;
    float s = 0.f;
#pragma unroll
    for (int w2 = 0; w2 < 8; w2++) s += pacc[w2][d];
    part[((size_t)b * NCHUNK + ch) * DMODEL + d] = s;
}

__global__ void mean2_kernel(const float* __restrict__ part,
                             const float* __restrict__ g,
                             const float* __restrict__ bo,
                             float* __restrict__ out) {
    int b = blockIdx.x, d = threadIdx.x;
    float s = 0.f;
    for (int c = 0; c < NCHUNK; c++) s += part[((size_t)b * NCHUNK + c) * DMODEL + d];
    out[b * DMODEL + d] = s * (1.0f / NTOK) * g[d] + bo[d];
}

// ---------------------------------------------------------------------------
// Launcher
// ---------------------------------------------------------------------------
extern "C" void kernel_launch(void* const* d_in, const int* in_sizes, int n_in,
                              void* d_out, int out_size) {
    const float* x       = (const float*)d_in[0];
    const float* patch_w = (const float*)d_in[1];
    const float* patch_b = (const float*)d_in[2];
    const float* pos     = (const float*)d_in[3];
    const float* imp_w1  = (const float*)d_in[4];
    const float* imp_b1  = (const float*)d_in[5];
    const float* imp_w2  = (const float*)d_in[6];
    const float* imp_b2  = (const float*)d_in[7];
    const float* ln1_g   = (const float*)d_in[8];
    const float* ln1_b   = (const float*)d_in[9];
    const float* qkv_w   = (const float*)d_in[10];
    const float* qkv_b   = (const float*)d_in[11];
    const float* proj_w  = (const float*)d_in[12];
    const float* proj_b  = (const float*)d_in[13];
    const float* ln2_g   = (const float*)d_in[14];
    const float* ln2_b   = (const float*)d_in[15];
    const float* mlp_w1  = (const float*)d_in[16];
    const float* mlp_b1  = (const float*)d_in[17];
    const float* mlp_w2  = (const float*)d_in[18];
    const float* mlp_b2  = (const float*)d_in[19];
    const float* out_g   = (const float*)d_in[20];
    const float* out_b   = (const float*)d_in[21];
    float* out = (float*)d_out;

    float *tokens, *hbuf, *scores, *part;
    __half *hln, *qkv, *attn, *mlp, *wt, *wimp;
    int *mask, *idx;
    cudaGetSymbolAddress((void**)&tokens, g_tokens);
    cudaGetSymbolAddress((void**)&hbuf,   g_h);
    cudaGetSymbolAddress((void**)&hln,    g_hln);
    cudaGetSymbolAddress((void**)&qkv,    g_qkv);
    cudaGetSymbolAddress((void**)&attn,   g_attn);
    cudaGetSymbolAddress((void**)&mlp,    g_mlp);
    cudaGetSymbolAddress((void**)&scores, g_scores);
    cudaGetSymbolAddress((void**)&mask,   g_mask);
    cudaGetSymbolAddress((void**)&idx,    g_idx);
    cudaGetSymbolAddress((void**)&part,   g_part);
    cudaGetSymbolAddress((void**)&wt,     g_wt);
    cudaGetSymbolAddress((void**)&wimp,   g_wimp);

    cudaFuncSetAttribute((const void*)gemm_fp16<OUT_QKV, 3>,
                         cudaFuncAttributeMaxDynamicSharedMemorySize, GEMM_SMEM(3));
    cudaFuncSetAttribute((const void*)gemm_fp16<OUT_GELU, 4>,
                         cudaFuncAttributeMaxDynamicSharedMemorySize, GEMM_SMEM(4));
    cudaFuncSetAttribute((const void*)gemm_fp16<OUT_RES, 2>,
                         cudaFuncAttributeMaxDynamicSharedMemorySize, GEMM_SMEM(2));
    cudaFuncSetAttribute((const void*)gemm_fp16<OUT_RELU, 2>,
                         cudaFuncAttributeMaxDynamicSharedMemorySize, GEMM_SMEM(2));

    dim3 tb(32, 8);

    transpose_w<<<dim3(24, 8, 3), tb>>>(qkv_w, wt + OFF_QKV, DMODEL, 768);              // 0
    patch_fused_kernel<<<MTOT, 256>>>(x, patch_w, patch_b, pos, ln1_g, ln1_b,
                                      tokens, hln, mlp);                                 // 1
    split_w_kernel<<<DMODEL, 256>>>(imp_w1, wimp);                                       // 2
    gemm_fp16<OUT_QKV, 3><<<dim3(6, 96), 256, GEMM_SMEM(3)>>>(
        hln, wt + OFF_QKV, qkv_b, nullptr, nullptr, qkv, MTOT, 768, DMODEL);             // 3
    gemm_fp16<OUT_RELU, 2><<<dim3(2, 144), 256, GEMM_SMEM(2)>>>(
        mlp, wimp, imp_b1, nullptr, hbuf, nullptr, MTOT, DMODEL, 768);                   // 4
    transpose_w<<<dim3(8, 8, 3), tb>>>(proj_w, wt + OFF_PROJ, DMODEL, DMODEL);           // 5
    transpose_w<<<dim3(32, 8, 3), tb>>>(mlp_w1, wt + OFF_MLP1, DMODEL, 1024);            // 6
    transpose_w<<<dim3(8, 32, 3), tb>>>(mlp_w2, wt + OFF_MLP2, 1024, DMODEL);            // 7
    score_kernel<<<MTOT / 8, 256>>>(hbuf, imp_w2, imp_b2, scores);                       // 8
    mask_kernel<<<MTOT / 8, 256>>>(scores, mask);                                        // 9
    compact_kernel<<<BATCH, 256>>>(mask, idx);                                           // 10

    for (int l = 0; l < DEPTH; l++) {
        if (l > 0) {
            ln_half_kernel<<<MTOT / 8, 256>>>(tokens, ln1_g + l * DMODEL,
                                              ln1_b + l * DMODEL, hln);
            gemm_fp16<OUT_QKV, 3><<<dim3(6, 96), 256, GEMM_SMEM(3)>>>(
                hln, wt + OFF_QKV + (size_t)l * DMODEL * 768, qkv_b + l * 768,
                nullptr, nullptr, qkv, MTOT, 768, DMODEL);
        }
        attn_fp16<<<dim3(NTOK / 256, NHEADS, BATCH), 256>>>(qkv, idx, attn);
        gemm_fp16<OUT_RES, 2><<<dim3(2, 144), 256, GEMM_SMEM(2)>>>(
            attn, wt + OFF_PROJ + (size_t)l * DMODEL * DMODEL, proj_b + l * DMODEL,
            tokens, tokens, nullptr, MTOT, DMODEL, DMODEL);
        ln_half_kernel<<<MTOT / 8, 256>>>(tokens, ln2_g + l * DMODEL,
                                          ln2_b + l * DMODEL, hln);
        gemm_fp16<OUT_GELU, 4><<<dim3(8, 72), 256, GEMM_SMEM(4)>>>(
            hln, wt + OFF_MLP1 + (size_t)l * DMODEL * 1024, mlp_b1 + l * 1024,
            nullptr, nullptr, mlp, MTOT, 1024, DMODEL);
        gemm_fp16<OUT_RES, 2><<<dim3(2, 144), 256, GEMM_SMEM(2)>>>(
            mlp, wt + OFF_MLP2 + (size_t)l * 1024 * DMODEL, mlp_b2 + l * DMODEL,
            tokens, tokens, nullptr, MTOT, DMODEL, 1024);
    }

    mean1_fused<<<dim3(NCHUNK, BATCH), 256>>>(tokens, part);
    mean2_kernel<<<BATCH, 256>>>(part, out_g, out_b, out);
}